// round 12
// baseline (speedup 1.0000x reference)
#include <cuda_runtime.h>
#include <cuda_bf16.h>
#include <math.h>
#include <float.h>

// ---------------- problem constants ----------------
// B=4, S=1024, IN=512, D=4096, F=16384, E=8, OUT=256, H=32, dh=128
#define TOK   4096
#define DMODEL 4096
#define DIN   512
#define FFN   16384
#define SEQ   1024
#define NHEAD 32
#define DHEAD 128
#define NEXP  8
#define NOUT  256

// ---------------- scratch (device globals; no allocation allowed) ----------------
__device__ float g_h0  [(size_t)TOK * DMODEL];
__device__ float g_a   [(size_t)TOK * DMODEL];
__device__ float g_q   [(size_t)TOK * DMODEL];
__device__ float g_k   [(size_t)TOK * DMODEL];
__device__ float g_v   [(size_t)TOK * DMODEL];
__device__ float g_attn[(size_t)TOK * DMODEL];
__device__ float g_h   [(size_t)TOK * DMODEL];
__device__ float g_sc  [(size_t)128 * SEQ * SEQ];       // 512 MB
__device__ float g_gbuf[(size_t)TOK * FFN];             // 256 MB
__device__ float g_ubuf[(size_t)TOK * FFN];             // 256 MB
__device__ float g_c   [TOK];
__device__ float g_cs  [NOUT];
// bf16 split buffers (activations [M][K], weights transposed [N][K])
__device__ __nv_bfloat16 g_Ahi[(size_t)TOK * FFN];      // 128 MB
__device__ __nv_bfloat16 g_Alo[(size_t)TOK * FFN];
__device__ __nv_bfloat16 g_Bhi[(size_t)FFN * DMODEL];   // 128 MB
__device__ __nv_bfloat16 g_Blo[(size_t)FFN * DMODEL];

// ================= bf16x3 tensor-core NT GEMM =================
// C[M][N] = A[M][K] @ Bt[N][K]^T  with A,Bt split into (hi,lo) bf16.
// 128x128 block tile, BK=32, 256 threads, 8 warps (2x4), warp tile 64x32.
// cp.async 2-stage pipeline, dynamic smem 80 KB.

__device__ __forceinline__ void mma16816(float* c, const unsigned* a,
                                         unsigned b0, unsigned b1)
{
    asm volatile(
        "mma.sync.aligned.m16n8k16.row.col.f32.bf16.bf16.f32 "
        "{%0,%1,%2,%3},{%4,%5,%6,%7},{%8,%9},{%0,%1,%2,%3};\n"
        : "+f"(c[0]), "+f"(c[1]), "+f"(c[2]), "+f"(c[3])
        : "r"(a[0]), "r"(a[1]), "r"(a[2]), "r"(a[3]), "r"(b0), "r"(b1));
}

__device__ __forceinline__ void cpa16(void* smem_dst, const void* gsrc)
{
    unsigned sa = (unsigned)__cvta_generic_to_shared(smem_dst);
    asm volatile("cp.async.cg.shared.global [%0], [%1], 16;\n" :: "r"(sa), "l"(gsrc));
}

#define TILE_E 5120      // 128 * 40 elements per smem tile
#define STAGE_E 20480    // 4 tiles per stage

__global__ __launch_bounds__(256, 1)
void gemm_bf3(const __nv_bfloat16* __restrict__ A_hi, const __nv_bfloat16* __restrict__ A_lo, int lda,
              const __nv_bfloat16* __restrict__ Bt_hi, const __nv_bfloat16* __restrict__ Bt_lo, int ldb,
              float* __restrict__ C, int ldc, int K,
              const float* __restrict__ bias, const float* __restrict__ resid)
{
    extern __shared__ __nv_bfloat16 sm[];

    const int m0 = blockIdx.y * 128;
    const int n0 = blockIdx.x * 128;
    const int tid = threadIdx.x;
    const int lane = tid & 31;
    const int wid = tid >> 5;
    const int warp_m = (wid >> 2) * 64;     // 0 or 64
    const int warp_n = (wid & 3) * 32;      // 0,32,64,96

    const int row  = tid >> 1;              // 0..127 (for both A and B tiles)
    const int half = tid & 1;               // 0/1 -> 16-element halves

    float acc[4][4][4];
#pragma unroll
    for (int i = 0; i < 4; ++i)
#pragma unroll
        for (int j = 0; j < 4; ++j)
#pragma unroll
            for (int t = 0; t < 4; ++t) acc[i][j][t] = 0.f;

    const int nit = K >> 5;   // K / 32

    // ---- stage copy helper (inlined logic) ----
    // stage st, k-offset k0
    auto issue = [&](int st, int k0) {
        __nv_bfloat16* Ah = sm + st * STAGE_E;
        __nv_bfloat16* Al = Ah + TILE_E;
        __nv_bfloat16* Bh = Ah + 2 * TILE_E;
        __nv_bfloat16* Bl = Ah + 3 * TILE_E;
        const __nv_bfloat16* gAh = A_hi  + (size_t)(m0 + row) * lda + k0 + half * 16;
        const __nv_bfloat16* gAl = A_lo  + (size_t)(m0 + row) * lda + k0 + half * 16;
        const __nv_bfloat16* gBh = Bt_hi + (size_t)(n0 + row) * ldb + k0 + half * 16;
        const __nv_bfloat16* gBl = Bt_lo + (size_t)(n0 + row) * ldb + k0 + half * 16;
        int so = row * 40 + half * 16;
        cpa16(&Ah[so],     gAh);     cpa16(&Ah[so + 8], gAh + 8);
        cpa16(&Al[so],     gAl);     cpa16(&Al[so + 8], gAl + 8);
        cpa16(&Bh[so],     gBh);     cpa16(&Bh[so + 8], gBh + 8);
        cpa16(&Bl[so],     gBl);     cpa16(&Bl[so + 8], gBl + 8);
    };

    issue(0, 0);
    asm volatile("cp.async.commit_group;\n");

    for (int it = 0; it < nit; ++it) {
        if (it + 1 < nit) issue((it + 1) & 1, (it + 1) * 32);
        asm volatile("cp.async.commit_group;\n");
        asm volatile("cp.async.wait_group 1;\n");
        __syncthreads();

        const __nv_bfloat16* Ah = sm + (it & 1) * STAGE_E;
        const __nv_bfloat16* Al = Ah + TILE_E;
        const __nv_bfloat16* Bh = Ah + 2 * TILE_E;
        const __nv_bfloat16* Bl = Ah + 3 * TILE_E;

#pragma unroll
        for (int kk = 0; kk < 32; kk += 16) {
            unsigned ah[4][4], al[4][4];
#pragma unroll
            for (int i = 0; i < 4; ++i) {
                int r = warp_m + i * 16 + (lane >> 2);
                int c = kk + (lane & 3) * 2;
                const __nv_bfloat16* p = Ah + r * 40 + c;
                ah[i][0] = *(const unsigned*)p;
                ah[i][1] = *(const unsigned*)(p + 8 * 40);
                ah[i][2] = *(const unsigned*)(p + 8);
                ah[i][3] = *(const unsigned*)(p + 8 * 40 + 8);
                const __nv_bfloat16* q = Al + r * 40 + c;
                al[i][0] = *(const unsigned*)q;
                al[i][1] = *(const unsigned*)(q + 8 * 40);
                al[i][2] = *(const unsigned*)(q + 8);
                al[i][3] = *(const unsigned*)(q + 8 * 40 + 8);
            }
#pragma unroll
            for (int j = 0; j < 4; ++j) {
                int rn = warp_n + j * 8 + (lane >> 2);
                int ck = kk + (lane & 3) * 2;
                const __nv_bfloat16* pb = Bh + rn * 40 + ck;
                unsigned bh0 = *(const unsigned*)pb;
                unsigned bh1 = *(const unsigned*)(pb + 8);
                const __nv_bfloat16* qb = Bl + rn * 40 + ck;
                unsigned bl0 = *(const unsigned*)qb;
                unsigned bl1 = *(const unsigned*)(qb + 8);
#pragma unroll
                for (int i = 0; i < 4; ++i) {
                    mma16816(acc[i][j], ah[i], bh0, bh1);   // hi*hi
                    mma16816(acc[i][j], al[i], bh0, bh1);   // lo*hi
                    mma16816(acc[i][j], ah[i], bl0, bl1);   // hi*lo
                }
            }
        }
        __syncthreads();
    }

    // ---- epilogue ----
#pragma unroll
    for (int i = 0; i < 4; ++i) {
        int r0 = m0 + warp_m + i * 16 + (lane >> 2);
#pragma unroll
        for (int j = 0; j < 4; ++j) {
            int cc = n0 + warp_n + j * 8 + (lane & 3) * 2;
            float2 v0 = make_float2(acc[i][j][0], acc[i][j][1]);  // row r0
            float2 v1 = make_float2(acc[i][j][2], acc[i][j][3]);  // row r0+8
            if (bias) {
                float b0 = bias[cc], b1 = bias[cc + 1];
                v0.x += b0; v0.y += b1; v1.x += b0; v1.y += b1;
            }
            if (resid) {
                float2 r0v = *(const float2*)&resid[(size_t)r0 * ldc + cc];
                float2 r1v = *(const float2*)&resid[(size_t)(r0 + 8) * ldc + cc];
                v0.x += r0v.x; v0.y += r0v.y; v1.x += r1v.x; v1.y += r1v.y;
            }
            *(float2*)&C[(size_t)r0 * ldc + cc] = v0;
            *(float2*)&C[(size_t)(r0 + 8) * ldc + cc] = v1;
        }
    }
}

// ---------------- fp32 -> (hi,lo) bf16 split, same layout ----------------
__global__ void cvt_split(const float* __restrict__ X,
                          __nv_bfloat16* __restrict__ hi, __nv_bfloat16* __restrict__ lo)
{
    size_t i = ((size_t)blockIdx.x * 256 + threadIdx.x) * 4;
    float4 v = *(const float4*)&X[i];
    __nv_bfloat16 h0 = __float2bfloat16_rn(v.x);
    __nv_bfloat16 h1 = __float2bfloat16_rn(v.y);
    __nv_bfloat16 h2 = __float2bfloat16_rn(v.z);
    __nv_bfloat16 h3 = __float2bfloat16_rn(v.w);
    __nv_bfloat16 l0 = __float2bfloat16_rn(v.x - __bfloat162float(h0));
    __nv_bfloat16 l1 = __float2bfloat16_rn(v.y - __bfloat162float(h1));
    __nv_bfloat16 l2 = __float2bfloat16_rn(v.z - __bfloat162float(h2));
    __nv_bfloat16 l3 = __float2bfloat16_rn(v.w - __bfloat162float(h3));
    __nv_bfloat162 p;
    p.x = h0; p.y = h1; *(__nv_bfloat162*)&hi[i]     = p;
    p.x = h2; p.y = h3; *(__nv_bfloat162*)&hi[i + 2] = p;
    p.x = l0; p.y = l1; *(__nv_bfloat162*)&lo[i]     = p;
    p.x = l2; p.y = l3; *(__nv_bfloat162*)&lo[i + 2] = p;
}

// ---------------- weight [K][N] fp32 -> transposed (hi,lo) bf16 [N][K] ----------------
__global__ void cvt_wt_t(const float* __restrict__ W,
                         __nv_bfloat16* __restrict__ bhi, __nv_bfloat16* __restrict__ blo,
                         int K, int N)
{
    __shared__ float t[32][33];
    int n0 = blockIdx.x * 32, k0 = blockIdx.y * 32;
    int tx = threadIdx.x, ty = threadIdx.y;   // 32 x 8
#pragma unroll
    for (int r = ty; r < 32; r += 8)
        t[r][tx] = W[(size_t)(k0 + r) * N + n0 + tx];
    __syncthreads();
#pragma unroll
    for (int r = ty; r < 32; r += 8) {
        float v = t[tx][r];                    // = W[k0+tx][n0+r]
        __nv_bfloat16 h = __float2bfloat16_rn(v);
        __nv_bfloat16 l = __float2bfloat16_rn(v - __bfloat162float(h));
        size_t o = (size_t)(n0 + r) * K + k0 + tx;
        bhi[o] = h; blo[o] = l;
    }
}

// ================= fp32 helper kernels (unchanged paths) =================

// generic fp32 SGEMM (kept for batched p@v)
__global__ __launch_bounds__(256, 2)
void sgemm_nn(const float* A, int lda, size_t sAo, size_t sAi,
              const float* B, int ldb, size_t sBo, size_t sBi,
              float*       C, int ldc, size_t sCo, size_t sCi,
              int K, int zshift,
              const float* bias, const float* resid)
{
    int z  = blockIdx.z;
    int zo = z >> zshift;
    int zi = z - (zo << zshift);
    A += (size_t)zo * sAo + (size_t)zi * sAi;
    B += (size_t)zo * sBo + (size_t)zi * sBi;
    C += (size_t)zo * sCo + (size_t)zi * sCi;
    if (resid) resid += (size_t)zo * sCo + (size_t)zi * sCi;

    const int m0 = blockIdx.y * 128;
    const int n0 = blockIdx.x * 128;
    const int tid = threadIdx.x;
    const int tx = tid & 15, ty = tid >> 4;

    __shared__ float As[16][128];
    __shared__ float Bs[16][128];

    float acc[8][8];
#pragma unroll
    for (int i = 0; i < 8; ++i)
#pragma unroll
        for (int j = 0; j < 8; ++j) acc[i][j] = 0.f;

    for (int k0 = 0; k0 < K; k0 += 16) {
#pragma unroll
        for (int j = 0; j < 2; ++j) {
            int i   = tid * 2 + j;
            int ar  = i >> 2;
            int ac4 = (i & 3) * 4;
            float4 va = *(const float4*)&A[(size_t)(m0 + ar) * lda + k0 + ac4];
            As[ac4 + 0][ar] = va.x; As[ac4 + 1][ar] = va.y;
            As[ac4 + 2][ar] = va.z; As[ac4 + 3][ar] = va.w;
            int br  = i >> 5;
            int bc4 = (i & 31) * 4;
            *(float4*)&Bs[br][bc4] = *(const float4*)&B[(size_t)(k0 + br) * ldb + n0 + bc4];
        }
        __syncthreads();
#pragma unroll
        for (int kk = 0; kk < 16; ++kk) {
            float a[8], b[8];
            *(float4*)&a[0] = *(float4*)&As[kk][ty * 8];
            *(float4*)&a[4] = *(float4*)&As[kk][ty * 8 + 4];
            *(float4*)&b[0] = *(float4*)&Bs[kk][tx * 8];
            *(float4*)&b[4] = *(float4*)&Bs[kk][tx * 8 + 4];
#pragma unroll
            for (int i = 0; i < 8; ++i)
#pragma unroll
                for (int j = 0; j < 8; ++j)
                    acc[i][j] = fmaf(a[i], b[j], acc[i][j]);
        }
        __syncthreads();
    }

#pragma unroll
    for (int i = 0; i < 8; ++i) {
        int rrow = m0 + ty * 8 + i;
#pragma unroll
        for (int jj = 0; jj < 2; ++jj) {
            int col = n0 + tx * 8 + jj * 4;
            float4 r;
            r.x = acc[i][jj * 4 + 0]; r.y = acc[i][jj * 4 + 1];
            r.z = acc[i][jj * 4 + 2]; r.w = acc[i][jj * 4 + 3];
            if (bias) {
                r.x += bias[col]; r.y += bias[col + 1];
                r.z += bias[col + 2]; r.w += bias[col + 3];
            }
            if (resid) {
                float4 rv = *(const float4*)&resid[(size_t)rrow * ldc + col];
                r.x += rv.x; r.y += rv.y; r.z += rv.z; r.w += rv.w;
            }
            *(float4*)&C[(size_t)rrow * ldc + col] = r;
        }
    }
}

// causal scores fp32
__global__ __launch_bounds__(256, 2)
void scores_nt(const float* __restrict__ Q, const float* __restrict__ Kt,
               float* __restrict__ Sc)
{
    int z = blockIdx.z;
    int b = z >> 5, h = z & 31;
    const float* A = Q  + (size_t)b * SEQ * DMODEL + (size_t)h * DHEAD;
    const float* B = Kt + (size_t)b * SEQ * DMODEL + (size_t)h * DHEAD;
    float*       C = Sc + (size_t)z * SEQ * SEQ;

    const int m0 = blockIdx.y * 128;
    const int n0 = blockIdx.x * 128;
    const int tid = threadIdx.x;
    const int tx = tid & 15, ty = tid >> 4;

    if (n0 > m0) {
        float4 neg = make_float4(-INFINITY, -INFINITY, -INFINITY, -INFINITY);
#pragma unroll
        for (int i = 0; i < 8; ++i) {
            int row = m0 + ty * 8 + i;
            *(float4*)&C[(size_t)row * SEQ + n0 + tx * 8]     = neg;
            *(float4*)&C[(size_t)row * SEQ + n0 + tx * 8 + 4] = neg;
        }
        return;
    }

    __shared__ float As[16][128];
    __shared__ float Bs[16][128];
    float acc[8][8];
#pragma unroll
    for (int i = 0; i < 8; ++i)
#pragma unroll
        for (int j = 0; j < 8; ++j) acc[i][j] = 0.f;

    for (int k0 = 0; k0 < DHEAD; k0 += 16) {
#pragma unroll
        for (int j = 0; j < 2; ++j) {
            int i   = tid * 2 + j;
            int r   = i >> 2;
            int c4  = (i & 3) * 4;
            float4 va = *(const float4*)&A[(size_t)(m0 + r) * DMODEL + k0 + c4];
            As[c4 + 0][r] = va.x; As[c4 + 1][r] = va.y;
            As[c4 + 2][r] = va.z; As[c4 + 3][r] = va.w;
            float4 vb = *(const float4*)&B[(size_t)(n0 + r) * DMODEL + k0 + c4];
            Bs[c4 + 0][r] = vb.x; Bs[c4 + 1][r] = vb.y;
            Bs[c4 + 2][r] = vb.z; Bs[c4 + 3][r] = vb.w;
        }
        __syncthreads();
#pragma unroll
        for (int kk = 0; kk < 16; ++kk) {
            float a[8], b[8];
            *(float4*)&a[0] = *(float4*)&As[kk][ty * 8];
            *(float4*)&a[4] = *(float4*)&As[kk][ty * 8 + 4];
            *(float4*)&b[0] = *(float4*)&Bs[kk][tx * 8];
            *(float4*)&b[4] = *(float4*)&Bs[kk][tx * 8 + 4];
#pragma unroll
            for (int i = 0; i < 8; ++i)
#pragma unroll
                for (int j = 0; j < 8; ++j)
                    acc[i][j] = fmaf(a[i], b[j], acc[i][j]);
        }
        __syncthreads();
    }

    const float scale = 0.08838834764831845f;
#pragma unroll
    for (int i = 0; i < 8; ++i) {
        int row = m0 + ty * 8 + i;
#pragma unroll
        for (int jj = 0; jj < 2; ++jj) {
            int col = n0 + tx * 8 + jj * 4;
            float4 r;
            r.x = (col     <= row) ? acc[i][jj*4+0] * scale : -INFINITY;
            r.y = (col + 1 <= row) ? acc[i][jj*4+1] * scale : -INFINITY;
            r.z = (col + 2 <= row) ? acc[i][jj*4+2] * scale : -INFINITY;
            r.w = (col + 3 <= row) ? acc[i][jj*4+3] * scale : -INFINITY;
            *(float4*)&C[(size_t)row * SEQ + col] = r;
        }
    }
}

__global__ void softmax_k(float* __restrict__ Sc)
{
    size_t base = (size_t)blockIdx.x * SEQ;
    int tid = threadIdx.x;
    float4 v = *(float4*)&Sc[base + (size_t)tid * 4];

    float m = fmaxf(fmaxf(v.x, v.y), fmaxf(v.z, v.w));
    __shared__ float red[8];
#pragma unroll
    for (int o = 16; o; o >>= 1) m = fmaxf(m, __shfl_xor_sync(0xffffffffu, m, o));
    if ((tid & 31) == 0) red[tid >> 5] = m;
    __syncthreads();
    if (tid < 32) {
        float t = (tid < 8) ? red[tid] : -INFINITY;
#pragma unroll
        for (int o = 4; o; o >>= 1) t = fmaxf(t, __shfl_xor_sync(0xffffffffu, t, o));
        if (tid == 0) red[0] = t;
    }
    __syncthreads();
    m = red[0];

    float e0 = expf(v.x - m), e1 = expf(v.y - m), e2 = expf(v.z - m), e3 = expf(v.w - m);
    float s = e0 + e1 + e2 + e3;
    __syncthreads();
#pragma unroll
    for (int o = 16; o; o >>= 1) s += __shfl_xor_sync(0xffffffffu, s, o);
    if ((tid & 31) == 0) red[tid >> 5] = s;
    __syncthreads();
    if (tid < 32) {
        float t = (tid < 8) ? red[tid] : 0.f;
#pragma unroll
        for (int o = 4; o; o >>= 1) t += __shfl_xor_sync(0xffffffffu, t, o);
        if (tid == 0) red[0] = t;
    }
    __syncthreads();
    float inv = 1.f / red[0];

    v.x = e0 * inv; v.y = e1 * inv; v.z = e2 * inv; v.w = e3 * inv;
    *(float4*)&Sc[base + (size_t)tid * 4] = v;
}

__global__ void rmsnorm_k(const float* __restrict__ X, const float* __restrict__ W,
                          float* __restrict__ Y)
{
    size_t base = (size_t)blockIdx.x * DMODEL;
    int tid = threadIdx.x;
    float4 v[4];
    float ss = 0.f;
#pragma unroll
    for (int u = 0; u < 4; ++u) {
        v[u] = *(const float4*)&X[base + (size_t)tid * 4 + (size_t)u * 1024];
        ss += v[u].x * v[u].x + v[u].y * v[u].y + v[u].z * v[u].z + v[u].w * v[u].w;
    }
    __shared__ float red[8];
#pragma unroll
    for (int o = 16; o; o >>= 1) ss += __shfl_xor_sync(0xffffffffu, ss, o);
    if ((tid & 31) == 0) red[tid >> 5] = ss;
    __syncthreads();
    if (tid < 32) {
        float t = (tid < 8) ? red[tid] : 0.f;
#pragma unroll
        for (int o = 4; o; o >>= 1) t += __shfl_xor_sync(0xffffffffu, t, o);
        if (tid == 0) red[0] = t;
    }
    __syncthreads();
    float r = rsqrtf(red[0] / (float)DMODEL + 1e-6f);
#pragma unroll
    for (int u = 0; u < 4; ++u) {
        float4 w4 = *(const float4*)&W[(size_t)tid * 4 + (size_t)u * 1024];
        float4 o;
        o.x = v[u].x * r * w4.x; o.y = v[u].y * r * w4.y;
        o.z = v[u].z * r * w4.z; o.w = v[u].w * r * w4.w;
        *(float4*)&Y[base + (size_t)tid * 4 + (size_t)u * 1024] = o;
    }
}

__global__ void silumul_k(float* __restrict__ G, const float* __restrict__ U)
{
    size_t i = ((size_t)blockIdx.x * blockDim.x + threadIdx.x) * 4;
    float4 g = *(float4*)&G[i];
    float4 u = *(const float4*)&U[i];
    g.x = g.x / (1.f + expf(-g.x)) * u.x;
    g.y = g.y / (1.f + expf(-g.y)) * u.y;
    g.z = g.z / (1.f + expf(-g.z)) * u.z;
    g.w = g.w / (1.f + expf(-g.w)) * u.w;
    *(float4*)&G[i] = g;
}

__global__ void router_k(const float* __restrict__ H, const float* __restrict__ Wr,
                         const float* __restrict__ br, float* __restrict__ cOut)
{
    int t = blockIdx.x;
    int tid = threadIdx.x;
    float p[NEXP];
#pragma unroll
    for (int e = 0; e < NEXP; ++e) p[e] = 0.f;
    const float* hrow = H + (size_t)t * DMODEL;
    for (int d = tid; d < DMODEL; d += 128) {
        float hv = hrow[d];
        const float* wr = &Wr[(size_t)d * NEXP];
#pragma unroll
        for (int e = 0; e < NEXP; ++e) p[e] = fmaf(hv, wr[e], p[e]);
    }
    __shared__ float red[NEXP * 128];
#pragma unroll
    for (int e = 0; e < NEXP; ++e) red[e * 128 + tid] = p[e];
    __syncthreads();
    for (int off = 64; off > 0; off >>= 1) {
        if (tid < off) {
#pragma unroll
            for (int e = 0; e < NEXP; ++e)
                red[e * 128 + tid] += red[e * 128 + tid + off];
        }
        __syncthreads();
    }
    if (tid == 0) {
        float lg[NEXP];
#pragma unroll
        for (int e = 0; e < NEXP; ++e) lg[e] = red[e * 128] + br[e];
        int i0 = 0;
#pragma unroll
        for (int e = 1; e < NEXP; ++e) if (lg[e] > lg[i0]) i0 = e;
        int i1 = (i0 == 0) ? 1 : 0;
#pragma unroll
        for (int e = 0; e < NEXP; ++e) {
            if (e == i0) continue;
            if (lg[e] > lg[i1]) i1 = e;
        }
        cOut[t] = 0.5f * (hrow[i0] + hrow[i1]);
    }
}

__global__ void colsum_k(const float* __restrict__ Wout, float* __restrict__ cs)
{
    int o = blockIdx.x;
    int tid = threadIdx.x;
    float s = 0.f;
    for (int d = tid; d < DMODEL; d += 256) s += Wout[(size_t)d * NOUT + o];
    __shared__ float red[8];
#pragma unroll
    for (int off = 16; off; off >>= 1) s += __shfl_xor_sync(0xffffffffu, s, off);
    if ((tid & 31) == 0) red[tid >> 5] = s;
    __syncthreads();
    if (tid < 32) {
        float t = (tid < 8) ? red[tid] : 0.f;
#pragma unroll
        for (int off = 4; off; off >>= 1) t += __shfl_xor_sync(0xffffffffu, t, off);
        if (tid == 0) cs[o] = t;
    }
}

__global__ void final_k(const float* __restrict__ c, const float* __restrict__ cs,
                        const float* __restrict__ bout, float* __restrict__ out)
{
    int t = blockIdx.x, o = threadIdx.x;
    out[(size_t)t * NOUT + o] = c[t] * cs[o] + bout[o];
}

// ---------------- launch ----------------
extern "C" void kernel_launch(void* const* d_in, const int* in_sizes, int n_in,
                              void* d_out, int out_size)
{
    const float* x    = (const float*)d_in[0];
    const float* Wi   = (const float*)d_in[1];
    const float* bi   = (const float*)d_in[2];
    const float* ln1w = (const float*)d_in[3];
    const float* Wq   = (const float*)d_in[4];
    const float* Wk   = (const float*)d_in[5];
    const float* Wv   = (const float*)d_in[6];
    const float* Wo   = (const float*)d_in[7];
    const float* ln2w = (const float*)d_in[8];
    const float* Wg   = (const float*)d_in[9];
    const float* Wu   = (const float*)d_in[10];
    const float* Wd   = (const float*)d_in[11];
    const float* Wr   = (const float*)d_in[12];
    const float* br   = (const float*)d_in[13];
    const float* Wout = (const float*)d_in[14];
    const float* bout = (const float*)d_in[15];
    float* out = (float*)d_out;

    float *h0, *a, *q, *k, *v, *attn, *h, *sc, *gb, *ub, *c, *cs;
    __nv_bfloat16 *Ahi, *Alo, *Bhi, *Blo;
    cudaGetSymbolAddress((void**)&h0,   g_h0);
    cudaGetSymbolAddress((void**)&a,    g_a);
    cudaGetSymbolAddress((void**)&q,    g_q);
    cudaGetSymbolAddress((void**)&k,    g_k);
    cudaGetSymbolAddress((void**)&v,    g_v);
    cudaGetSymbolAddress((void**)&attn, g_attn);
    cudaGetSymbolAddress((void**)&h,    g_h);
    cudaGetSymbolAddress((void**)&sc,   g_sc);
    cudaGetSymbolAddress((void**)&gb,   g_gbuf);
    cudaGetSymbolAddress((void**)&ub,   g_ubuf);
    cudaGetSymbolAddress((void**)&c,    g_c);
    cudaGetSymbolAddress((void**)&cs,   g_cs);
    cudaGetSymbolAddress((void**)&Ahi,  g_Ahi);
    cudaGetSymbolAddress((void**)&Alo,  g_Alo);
    cudaGetSymbolAddress((void**)&Bhi,  g_Bhi);
    cudaGetSymbolAddress((void**)&Blo,  g_Blo);

    static bool attr_set = false;
    if (!attr_set) {
        cudaFuncSetAttribute(gemm_bf3, cudaFuncAttributeMaxDynamicSharedMemorySize, 81920);
        attr_set = true;
    }
    const size_t GSM = 81920;

    // 1. h0 = x @ Wi + bi
    cvt_split<<<(TOK * DIN) / 1024, 256>>>(x, Ahi, Alo);
    cvt_wt_t<<<dim3(DMODEL / 32, DIN / 32), dim3(32, 8)>>>(Wi, Bhi, Blo, DIN, DMODEL);
    gemm_bf3<<<dim3(32, 32), 256, GSM>>>(Ahi, Alo, DIN, Bhi, Blo, DIN,
                                         h0, DMODEL, DIN, bi, nullptr);
    // 2. a = rmsnorm(h0, ln1)
    rmsnorm_k<<<TOK, 256>>>(h0, ln1w, a);
    // 3. q,k,v = a @ {Wq,Wk,Wv}  (A conversion shared)
    cvt_split<<<((size_t)TOK * DMODEL) / 1024, 256>>>(a, Ahi, Alo);
    cvt_wt_t<<<dim3(DMODEL / 32, DMODEL / 32), dim3(32, 8)>>>(Wq, Bhi, Blo, DMODEL, DMODEL);
    gemm_bf3<<<dim3(32, 32), 256, GSM>>>(Ahi, Alo, DMODEL, Bhi, Blo, DMODEL,
                                         q, DMODEL, DMODEL, nullptr, nullptr);
    cvt_wt_t<<<dim3(DMODEL / 32, DMODEL / 32), dim3(32, 8)>>>(Wk, Bhi, Blo, DMODEL, DMODEL);
    gemm_bf3<<<dim3(32, 32), 256, GSM>>>(Ahi, Alo, DMODEL, Bhi, Blo, DMODEL,
                                         k, DMODEL, DMODEL, nullptr, nullptr);
    cvt_wt_t<<<dim3(DMODEL / 32, DMODEL / 32), dim3(32, 8)>>>(Wv, Bhi, Blo, DMODEL, DMODEL);
    gemm_bf3<<<dim3(32, 32), 256, GSM>>>(Ahi, Alo, DMODEL, Bhi, Blo, DMODEL,
                                         v, DMODEL, DMODEL, nullptr, nullptr);
    // 4-6. attention (fp32 path)
    scores_nt<<<dim3(8, 8, 128), 256>>>(q, k, sc);
    softmax_k<<<128 * SEQ, 256>>>(sc);
    sgemm_nn<<<dim3(1, 8, 128), 256>>>(
        sc, SEQ, (size_t)32 * SEQ * SEQ, (size_t)SEQ * SEQ,
        v, DMODEL, (size_t)SEQ * DMODEL, (size_t)DHEAD,
        attn, DMODEL, (size_t)SEQ * DMODEL, (size_t)DHEAD,
        SEQ, 5, nullptr, nullptr);
    // 7. h = h0 + attn @ Wo
    cvt_split<<<((size_t)TOK * DMODEL) / 1024, 256>>>(attn, Ahi, Alo);
    cvt_wt_t<<<dim3(DMODEL / 32, DMODEL / 32), dim3(32, 8)>>>(Wo, Bhi, Blo, DMODEL, DMODEL);
    gemm_bf3<<<dim3(32, 32), 256, GSM>>>(Ahi, Alo, DMODEL, Bhi, Blo, DMODEL,
                                         h, DMODEL, DMODEL, nullptr, h0);
    // 8. m = rmsnorm(h, ln2)
    rmsnorm_k<<<TOK, 256>>>(h, ln2w, a);
    // 9. g = m @ Wg ; u = m @ Wu
    cvt_split<<<((size_t)TOK * DMODEL) / 1024, 256>>>(a, Ahi, Alo);
    cvt_wt_t<<<dim3(FFN / 32, DMODEL / 32), dim3(32, 8)>>>(Wg, Bhi, Blo, DMODEL, FFN);
    gemm_bf3<<<dim3(128, 32), 256, GSM>>>(Ahi, Alo, DMODEL, Bhi, Blo, DMODEL,
                                          gb, FFN, DMODEL, nullptr, nullptr);
    cvt_wt_t<<<dim3(FFN / 32, DMODEL / 32), dim3(32, 8)>>>(Wu, Bhi, Blo, DMODEL, FFN);
    gemm_bf3<<<dim3(128, 32), 256, GSM>>>(Ahi, Alo, DMODEL, Bhi, Blo, DMODEL,
                                          ub, FFN, DMODEL, nullptr, nullptr);
    // 10. t = silu(g) * u
    silumul_k<<<((size_t)TOK * FFN) / (256 * 4), 256>>>(gb, ub);
    // 11. h = h + t @ Wd
    cvt_split<<<((size_t)TOK * FFN) / 1024, 256>>>(gb, Ahi, Alo);
    cvt_wt_t<<<dim3(DMODEL / 32, FFN / 32), dim3(32, 8)>>>(Wd, Bhi, Blo, FFN, DMODEL);
    gemm_bf3<<<dim3(32, 32), 256, GSM>>>(Ahi, Alo, FFN, Bhi, Blo, FFN,
                                         h, DMODEL, FFN, nullptr, h);
    // 12-13. router + output
    router_k<<<TOK, 128>>>(h, Wr, br, c);
    colsum_k<<<NOUT, 256>>>(Wout, cs);
    final_k<<<TOK, NOUT>>>(c, cs, bout, out);
}

// round 13
// speedup vs baseline: 1.0524x; 1.0524x over previous
#include <cuda_runtime.h>
#include <cuda_bf16.h>
#include <math.h>
#include <float.h>

// ---------------- problem constants ----------------
#define TOK   4096
#define DMODEL 4096
#define DIN   512
#define FFN   16384
#define SEQ   1024
#define NHEAD 32
#define DHEAD 128
#define NEXP  8
#define NOUT  256

// ---------------- scratch ----------------
__device__ float g_h0  [(size_t)TOK * DMODEL];
__device__ float g_a   [(size_t)TOK * DMODEL];
__device__ float g_q   [(size_t)TOK * DMODEL];
__device__ float g_k   [(size_t)TOK * DMODEL];
__device__ float g_v   [(size_t)TOK * DMODEL];
__device__ float g_attn[(size_t)TOK * DMODEL];
__device__ float g_h   [(size_t)TOK * DMODEL];
__device__ float g_sc  [(size_t)128 * SEQ * SEQ];
__device__ float g_gbuf[(size_t)TOK * FFN];
__device__ float g_ubuf[(size_t)TOK * FFN];
__device__ float g_c   [TOK];
__device__ float g_cs  [NOUT];
__device__ __nv_bfloat16 g_Ahi[(size_t)TOK * FFN];
__device__ __nv_bfloat16 g_Alo[(size_t)TOK * FFN];
__device__ __nv_bfloat16 g_Bhi[(size_t)FFN * DMODEL];
__device__ __nv_bfloat16 g_Blo[(size_t)FFN * DMODEL];

// ================= bf16x3 tensor-core NT GEMM (ldmatrix + 3-stage) =================
__device__ __forceinline__ void mma16816(float* c, const unsigned* a,
                                         unsigned b0, unsigned b1)
{
    asm volatile(
        "mma.sync.aligned.m16n8k16.row.col.f32.bf16.bf16.f32 "
        "{%0,%1,%2,%3},{%4,%5,%6,%7},{%8,%9},{%0,%1,%2,%3};\n"
        : "+f"(c[0]), "+f"(c[1]), "+f"(c[2]), "+f"(c[3])
        : "r"(a[0]), "r"(a[1]), "r"(a[2]), "r"(a[3]), "r"(b0), "r"(b1));
}

__device__ __forceinline__ void cpa16(void* smem_dst, const void* gsrc)
{
    unsigned sa = (unsigned)__cvta_generic_to_shared(smem_dst);
    asm volatile("cp.async.cg.shared.global [%0], [%1], 16;\n" :: "r"(sa), "l"(gsrc));
}

__device__ __forceinline__ void ldm_x4(unsigned* r, const __nv_bfloat16* p)
{
    unsigned sa = (unsigned)__cvta_generic_to_shared(p);
    asm volatile("ldmatrix.sync.aligned.m8n8.x4.shared.b16 {%0,%1,%2,%3}, [%4];\n"
                 : "=r"(r[0]), "=r"(r[1]), "=r"(r[2]), "=r"(r[3]) : "r"(sa));
}

#define TILE_E  5120      // 128 rows * 40 elems
#define STAGE_E 20480     // 4 tiles (Ahi,Alo,Bhi,Blo)
#define NSTAGE  3

__global__ __launch_bounds__(256, 1)
void gemm_bf3(const __nv_bfloat16* __restrict__ A_hi, const __nv_bfloat16* __restrict__ A_lo, int lda,
              const __nv_bfloat16* __restrict__ Bt_hi, const __nv_bfloat16* __restrict__ Bt_lo, int ldb,
              float* __restrict__ C, int ldc, int K,
              const float* __restrict__ bias, const float* __restrict__ resid)
{
    extern __shared__ __nv_bfloat16 sm[];

    const int m0 = blockIdx.y * 128;
    const int n0 = blockIdx.x * 128;
    const int tid = threadIdx.x;
    const int lane = tid & 31;
    const int wid = tid >> 5;
    const int warp_m = (wid >> 2) * 64;
    const int warp_n = (wid & 3) * 32;

    const int row  = tid >> 1;
    const int half = tid & 1;

    float acc[4][4][4];
#pragma unroll
    for (int i = 0; i < 4; ++i)
#pragma unroll
        for (int j = 0; j < 4; ++j)
#pragma unroll
            for (int t = 0; t < 4; ++t) acc[i][j][t] = 0.f;

    const int nit = K >> 5;

    auto issue = [&](int st, int k0) {
        __nv_bfloat16* Ah = sm + st * STAGE_E;
        __nv_bfloat16* Al = Ah + TILE_E;
        __nv_bfloat16* Bh = Ah + 2 * TILE_E;
        __nv_bfloat16* Bl = Ah + 3 * TILE_E;
        const __nv_bfloat16* gAh = A_hi  + (size_t)(m0 + row) * lda + k0 + half * 16;
        const __nv_bfloat16* gAl = A_lo  + (size_t)(m0 + row) * lda + k0 + half * 16;
        const __nv_bfloat16* gBh = Bt_hi + (size_t)(n0 + row) * ldb + k0 + half * 16;
        const __nv_bfloat16* gBl = Bt_lo + (size_t)(n0 + row) * ldb + k0 + half * 16;
        int so = row * 40 + half * 16;
        cpa16(&Ah[so],     gAh);     cpa16(&Ah[so + 8], gAh + 8);
        cpa16(&Al[so],     gAl);     cpa16(&Al[so + 8], gAl + 8);
        cpa16(&Bh[so],     gBh);     cpa16(&Bh[so + 8], gBh + 8);
        cpa16(&Bl[so],     gBl);     cpa16(&Bl[so + 8], gBl + 8);
    };

    // prologue: fill 2 stages
    issue(0, 0);
    asm volatile("cp.async.commit_group;\n");
    if (nit > 1) issue(1, 32);
    asm volatile("cp.async.commit_group;\n");

    // per-lane ldmatrix row offsets (element units, stride 40)
    const int a_r  = (lane & 15);            // row within 16
    const int a_c  = (lane >> 4) * 8;        // k half
    const int b_r  = (lane & 7) + ((lane >> 4) << 3);   // n within 16
    const int b_c  = ((lane >> 3) & 1) * 8;  // k half

    for (int it = 0; it < nit; ++it) {
        asm volatile("cp.async.wait_group 1;\n");
        __syncthreads();

        // prefetch stage it+2 (overwrites stage it-1, safe after the sync)
        if (it + 2 < nit) issue((it + 2) % NSTAGE, (it + 2) * 32);
        asm volatile("cp.async.commit_group;\n");

        const __nv_bfloat16* Ah = sm + (it % NSTAGE) * STAGE_E;
        const __nv_bfloat16* Al = Ah + TILE_E;
        const __nv_bfloat16* Bh = Ah + 2 * TILE_E;
        const __nv_bfloat16* Bl = Ah + 3 * TILE_E;

#pragma unroll
        for (int kk = 0; kk < 32; kk += 16) {
            unsigned ah[4][4], al[4][4];
#pragma unroll
            for (int i = 0; i < 4; ++i) {
                const __nv_bfloat16* pa = Ah + (warp_m + i * 16 + a_r) * 40 + kk + a_c;
                ldm_x4(ah[i], pa);
                const __nv_bfloat16* qa = Al + (warp_m + i * 16 + a_r) * 40 + kk + a_c;
                ldm_x4(al[i], qa);
            }
            unsigned bh[2][4], bl[2][4];
#pragma unroll
            for (int jj = 0; jj < 2; ++jj) {
                const __nv_bfloat16* pb = Bh + (warp_n + jj * 16 + b_r) * 40 + kk + b_c;
                ldm_x4(bh[jj], pb);
                const __nv_bfloat16* qb = Bl + (warp_n + jj * 16 + b_r) * 40 + kk + b_c;
                ldm_x4(bl[jj], qb);
            }
#pragma unroll
            for (int j = 0; j < 4; ++j) {
                unsigned bh0 = bh[j >> 1][(j & 1) * 2], bh1 = bh[j >> 1][(j & 1) * 2 + 1];
                unsigned bl0 = bl[j >> 1][(j & 1) * 2], bl1 = bl[j >> 1][(j & 1) * 2 + 1];
#pragma unroll
                for (int i = 0; i < 4; ++i) {
                    mma16816(acc[i][j], ah[i], bh0, bh1);   // hi*hi
                    mma16816(acc[i][j], al[i], bh0, bh1);   // lo*hi
                    mma16816(acc[i][j], ah[i], bl0, bl1);   // hi*lo
                }
            }
        }
        __syncthreads();
    }

    // ---- epilogue ----
#pragma unroll
    for (int i = 0; i < 4; ++i) {
        int r0 = m0 + warp_m + i * 16 + (lane >> 2);
#pragma unroll
        for (int j = 0; j < 4; ++j) {
            int cc = n0 + warp_n + j * 8 + (lane & 3) * 2;
            float2 v0 = make_float2(acc[i][j][0], acc[i][j][1]);
            float2 v1 = make_float2(acc[i][j][2], acc[i][j][3]);
            if (bias) {
                float b0 = bias[cc], b1 = bias[cc + 1];
                v0.x += b0; v0.y += b1; v1.x += b0; v1.y += b1;
            }
            if (resid) {
                float2 r0v = *(const float2*)&resid[(size_t)r0 * ldc + cc];
                float2 r1v = *(const float2*)&resid[(size_t)(r0 + 8) * ldc + cc];
                v0.x += r0v.x; v0.y += r0v.y; v1.x += r1v.x; v1.y += r1v.y;
            }
            *(float2*)&C[(size_t)r0 * ldc + cc] = v0;
            *(float2*)&C[(size_t)(r0 + 8) * ldc + cc] = v1;
        }
    }
}

// ---------------- fp32 -> (hi,lo) bf16 split ----------------
__global__ void cvt_split(const float* __restrict__ X,
                          __nv_bfloat16* __restrict__ hi, __nv_bfloat16* __restrict__ lo)
{
    size_t i = ((size_t)blockIdx.x * 256 + threadIdx.x) * 4;
    float4 v = *(const float4*)&X[i];
    __nv_bfloat16 h0 = __float2bfloat16_rn(v.x);
    __nv_bfloat16 h1 = __float2bfloat16_rn(v.y);
    __nv_bfloat16 h2 = __float2bfloat16_rn(v.z);
    __nv_bfloat16 h3 = __float2bfloat16_rn(v.w);
    __nv_bfloat16 l0 = __float2bfloat16_rn(v.x - __bfloat162float(h0));
    __nv_bfloat16 l1 = __float2bfloat16_rn(v.y - __bfloat162float(h1));
    __nv_bfloat16 l2 = __float2bfloat16_rn(v.z - __bfloat162float(h2));
    __nv_bfloat16 l3 = __float2bfloat16_rn(v.w - __bfloat162float(h3));
    __nv_bfloat162 p;
    p.x = h0; p.y = h1; *(__nv_bfloat162*)&hi[i]     = p;
    p.x = h2; p.y = h3; *(__nv_bfloat162*)&hi[i + 2] = p;
    p.x = l0; p.y = l1; *(__nv_bfloat162*)&lo[i]     = p;
    p.x = l2; p.y = l3; *(__nv_bfloat162*)&lo[i + 2] = p;
}

// ---------------- weight [K][N] -> transposed (hi,lo) bf16 [N][K] ----------------
__global__ void cvt_wt_t(const float* __restrict__ W,
                         __nv_bfloat16* __restrict__ bhi, __nv_bfloat16* __restrict__ blo,
                         int K, int N)
{
    __shared__ float t[32][33];
    int n0 = blockIdx.x * 32, k0 = blockIdx.y * 32;
    int tx = threadIdx.x, ty = threadIdx.y;
#pragma unroll
    for (int r = ty; r < 32; r += 8)
        t[r][tx] = W[(size_t)(k0 + r) * N + n0 + tx];
    __syncthreads();
#pragma unroll
    for (int r = ty; r < 32; r += 8) {
        float v = t[tx][r];
        __nv_bfloat16 h = __float2bfloat16_rn(v);
        __nv_bfloat16 l = __float2bfloat16_rn(v - __bfloat162float(h));
        size_t o = (size_t)(n0 + r) * K + k0 + tx;
        bhi[o] = h; blo[o] = l;
    }
}

// ================= fp32 helper kernels =================
__global__ __launch_bounds__(256, 2)
void sgemm_nn(const float* A, int lda, size_t sAo, size_t sAi,
              const float* B, int ldb, size_t sBo, size_t sBi,
              float*       C, int ldc, size_t sCo, size_t sCi,
              int K, int zshift,
              const float* bias, const float* resid)
{
    int z  = blockIdx.z;
    int zo = z >> zshift;
    int zi = z - (zo << zshift);
    A += (size_t)zo * sAo + (size_t)zi * sAi;
    B += (size_t)zo * sBo + (size_t)zi * sBi;
    C += (size_t)zo * sCo + (size_t)zi * sCi;
    if (resid) resid += (size_t)zo * sCo + (size_t)zi * sCi;

    const int m0 = blockIdx.y * 128;
    const int n0 = blockIdx.x * 128;
    const int tid = threadIdx.x;
    const int tx = tid & 15, ty = tid >> 4;

    __shared__ float As[16][128];
    __shared__ float Bs[16][128];

    float acc[8][8];
#pragma unroll
    for (int i = 0; i < 8; ++i)
#pragma unroll
        for (int j = 0; j < 8; ++j) acc[i][j] = 0.f;

    for (int k0 = 0; k0 < K; k0 += 16) {
#pragma unroll
        for (int j = 0; j < 2; ++j) {
            int i   = tid * 2 + j;
            int ar  = i >> 2;
            int ac4 = (i & 3) * 4;
            float4 va = *(const float4*)&A[(size_t)(m0 + ar) * lda + k0 + ac4];
            As[ac4 + 0][ar] = va.x; As[ac4 + 1][ar] = va.y;
            As[ac4 + 2][ar] = va.z; As[ac4 + 3][ar] = va.w;
            int br  = i >> 5;
            int bc4 = (i & 31) * 4;
            *(float4*)&Bs[br][bc4] = *(const float4*)&B[(size_t)(k0 + br) * ldb + n0 + bc4];
        }
        __syncthreads();
#pragma unroll
        for (int kk = 0; kk < 16; ++kk) {
            float a[8], b[8];
            *(float4*)&a[0] = *(float4*)&As[kk][ty * 8];
            *(float4*)&a[4] = *(float4*)&As[kk][ty * 8 + 4];
            *(float4*)&b[0] = *(float4*)&Bs[kk][tx * 8];
            *(float4*)&b[4] = *(float4*)&Bs[kk][tx * 8 + 4];
#pragma unroll
            for (int i = 0; i < 8; ++i)
#pragma unroll
                for (int j = 0; j < 8; ++j)
                    acc[i][j] = fmaf(a[i], b[j], acc[i][j]);
        }
        __syncthreads();
    }

#pragma unroll
    for (int i = 0; i < 8; ++i) {
        int rrow = m0 + ty * 8 + i;
#pragma unroll
        for (int jj = 0; jj < 2; ++jj) {
            int col = n0 + tx * 8 + jj * 4;
            float4 r;
            r.x = acc[i][jj * 4 + 0]; r.y = acc[i][jj * 4 + 1];
            r.z = acc[i][jj * 4 + 2]; r.w = acc[i][jj * 4 + 3];
            if (bias) {
                r.x += bias[col]; r.y += bias[col + 1];
                r.z += bias[col + 2]; r.w += bias[col + 3];
            }
            if (resid) {
                float4 rv = *(const float4*)&resid[(size_t)rrow * ldc + col];
                r.x += rv.x; r.y += rv.y; r.z += rv.z; r.w += rv.w;
            }
            *(float4*)&C[(size_t)rrow * ldc + col] = r;
        }
    }
}

__global__ __launch_bounds__(256, 2)
void scores_nt(const float* __restrict__ Q, const float* __restrict__ Kt,
               float* __restrict__ Sc)
{
    int z = blockIdx.z;
    int b = z >> 5, h = z & 31;
    const float* A = Q  + (size_t)b * SEQ * DMODEL + (size_t)h * DHEAD;
    const float* B = Kt + (size_t)b * SEQ * DMODEL + (size_t)h * DHEAD;
    float*       C = Sc + (size_t)z * SEQ * SEQ;

    const int m0 = blockIdx.y * 128;
    const int n0 = blockIdx.x * 128;
    const int tid = threadIdx.x;
    const int tx = tid & 15, ty = tid >> 4;

    if (n0 > m0) {
        float4 neg = make_float4(-INFINITY, -INFINITY, -INFINITY, -INFINITY);
#pragma unroll
        for (int i = 0; i < 8; ++i) {
            int row = m0 + ty * 8 + i;
            *(float4*)&C[(size_t)row * SEQ + n0 + tx * 8]     = neg;
            *(float4*)&C[(size_t)row * SEQ + n0 + tx * 8 + 4] = neg;
        }
        return;
    }

    __shared__ float As[16][128];
    __shared__ float Bs[16][128];
    float acc[8][8];
#pragma unroll
    for (int i = 0; i < 8; ++i)
#pragma unroll
        for (int j = 0; j < 8; ++j) acc[i][j] = 0.f;

    for (int k0 = 0; k0 < DHEAD; k0 += 16) {
#pragma unroll
        for (int j = 0; j < 2; ++j) {
            int i   = tid * 2 + j;
            int r   = i >> 2;
            int c4  = (i & 3) * 4;
            float4 va = *(const float4*)&A[(size_t)(m0 + r) * DMODEL + k0 + c4];
            As[c4 + 0][r] = va.x; As[c4 + 1][r] = va.y;
            As[c4 + 2][r] = va.z; As[c4 + 3][r] = va.w;
            float4 vb = *(const float4*)&B[(size_t)(n0 + r) * DMODEL + k0 + c4];
            Bs[c4 + 0][r] = vb.x; Bs[c4 + 1][r] = vb.y;
            Bs[c4 + 2][r] = vb.z; Bs[c4 + 3][r] = vb.w;
        }
        __syncthreads();
#pragma unroll
        for (int kk = 0; kk < 16; ++kk) {
            float a[8], b[8];
            *(float4*)&a[0] = *(float4*)&As[kk][ty * 8];
            *(float4*)&a[4] = *(float4*)&As[kk][ty * 8 + 4];
            *(float4*)&b[0] = *(float4*)&Bs[kk][tx * 8];
            *(float4*)&b[4] = *(float4*)&Bs[kk][tx * 8 + 4];
#pragma unroll
            for (int i = 0; i < 8; ++i)
#pragma unroll
                for (int j = 0; j < 8; ++j)
                    acc[i][j] = fmaf(a[i], b[j], acc[i][j]);
        }
        __syncthreads();
    }

    const float scale = 0.08838834764831845f;
#pragma unroll
    for (int i = 0; i < 8; ++i) {
        int row = m0 + ty * 8 + i;
#pragma unroll
        for (int jj = 0; jj < 2; ++jj) {
            int col = n0 + tx * 8 + jj * 4;
            float4 r;
            r.x = (col     <= row) ? acc[i][jj*4+0] * scale : -INFINITY;
            r.y = (col + 1 <= row) ? acc[i][jj*4+1] * scale : -INFINITY;
            r.z = (col + 2 <= row) ? acc[i][jj*4+2] * scale : -INFINITY;
            r.w = (col + 3 <= row) ? acc[i][jj*4+3] * scale : -INFINITY;
            *(float4*)&C[(size_t)row * SEQ + col] = r;
        }
    }
}

__global__ void softmax_k(float* __restrict__ Sc)
{
    size_t base = (size_t)blockIdx.x * SEQ;
    int tid = threadIdx.x;
    float4 v = *(float4*)&Sc[base + (size_t)tid * 4];

    float m = fmaxf(fmaxf(v.x, v.y), fmaxf(v.z, v.w));
    __shared__ float red[8];
#pragma unroll
    for (int o = 16; o; o >>= 1) m = fmaxf(m, __shfl_xor_sync(0xffffffffu, m, o));
    if ((tid & 31) == 0) red[tid >> 5] = m;
    __syncthreads();
    if (tid < 32) {
        float t = (tid < 8) ? red[tid] : -INFINITY;
#pragma unroll
        for (int o = 4; o; o >>= 1) t = fmaxf(t, __shfl_xor_sync(0xffffffffu, t, o));
        if (tid == 0) red[0] = t;
    }
    __syncthreads();
    m = red[0];

    float e0 = expf(v.x - m), e1 = expf(v.y - m), e2 = expf(v.z - m), e3 = expf(v.w - m);
    float s = e0 + e1 + e2 + e3;
    __syncthreads();
#pragma unroll
    for (int o = 16; o; o >>= 1) s += __shfl_xor_sync(0xffffffffu, s, o);
    if ((tid & 31) == 0) red[tid >> 5] = s;
    __syncthreads();
    if (tid < 32) {
        float t = (tid < 8) ? red[tid] : 0.f;
#pragma unroll
        for (int o = 4; o; o >>= 1) t += __shfl_xor_sync(0xffffffffu, t, o);
        if (tid == 0) red[0] = t;
    }
    __syncthreads();
    float inv = 1.f / red[0];

    v.x = e0 * inv; v.y = e1 * inv; v.z = e2 * inv; v.w = e3 * inv;
    *(float4*)&Sc[base + (size_t)tid * 4] = v;
}

__global__ void rmsnorm_k(const float* __restrict__ X, const float* __restrict__ W,
                          float* __restrict__ Y)
{
    size_t base = (size_t)blockIdx.x * DMODEL;
    int tid = threadIdx.x;
    float4 v[4];
    float ss = 0.f;
#pragma unroll
    for (int u = 0; u < 4; ++u) {
        v[u] = *(const float4*)&X[base + (size_t)tid * 4 + (size_t)u * 1024];
        ss += v[u].x * v[u].x + v[u].y * v[u].y + v[u].z * v[u].z + v[u].w * v[u].w;
    }
    __shared__ float red[8];
#pragma unroll
    for (int o = 16; o; o >>= 1) ss += __shfl_xor_sync(0xffffffffu, ss, o);
    if ((tid & 31) == 0) red[tid >> 5] = ss;
    __syncthreads();
    if (tid < 32) {
        float t = (tid < 8) ? red[tid] : 0.f;
#pragma unroll
        for (int o = 4; o; o >>= 1) t += __shfl_xor_sync(0xffffffffu, t, o);
        if (tid == 0) red[0] = t;
    }
    __syncthreads();
    float r = rsqrtf(red[0] / (float)DMODEL + 1e-6f);
#pragma unroll
    for (int u = 0; u < 4; ++u) {
        float4 w4 = *(const float4*)&W[(size_t)tid * 4 + (size_t)u * 1024];
        float4 o;
        o.x = v[u].x * r * w4.x; o.y = v[u].y * r * w4.y;
        o.z = v[u].z * r * w4.z; o.w = v[u].w * r * w4.w;
        *(float4*)&Y[base + (size_t)tid * 4 + (size_t)u * 1024] = o;
    }
}

__global__ void silumul_k(float* __restrict__ G, const float* __restrict__ U)
{
    size_t i = ((size_t)blockIdx.x * blockDim.x + threadIdx.x) * 4;
    float4 g = *(float4*)&G[i];
    float4 u = *(const float4*)&U[i];
    g.x = g.x / (1.f + expf(-g.x)) * u.x;
    g.y = g.y / (1.f + expf(-g.y)) * u.y;
    g.z = g.z / (1.f + expf(-g.z)) * u.z;
    g.w = g.w / (1.f + expf(-g.w)) * u.w;
    *(float4*)&G[i] = g;
}

__global__ void router_k(const float* __restrict__ H, const float* __restrict__ Wr,
                         const float* __restrict__ br, float* __restrict__ cOut)
{
    int t = blockIdx.x;
    int tid = threadIdx.x;
    float p[NEXP];
#pragma unroll
    for (int e = 0; e < NEXP; ++e) p[e] = 0.f;
    const float* hrow = H + (size_t)t * DMODEL;
    for (int d = tid; d < DMODEL; d += 128) {
        float hv = hrow[d];
        const float* wr = &Wr[(size_t)d * NEXP];
#pragma unroll
        for (int e = 0; e < NEXP; ++e) p[e] = fmaf(hv, wr[e], p[e]);
    }
    __shared__ float red[NEXP * 128];
#pragma unroll
    for (int e = 0; e < NEXP; ++e) red[e * 128 + tid] = p[e];
    __syncthreads();
    for (int off = 64; off > 0; off >>= 1) {
        if (tid < off) {
#pragma unroll
            for (int e = 0; e < NEXP; ++e)
                red[e * 128 + tid] += red[e * 128 + tid + off];
        }
        __syncthreads();
    }
    if (tid == 0) {
        float lg[NEXP];
#pragma unroll
        for (int e = 0; e < NEXP; ++e) lg[e] = red[e * 128] + br[e];
        int i0 = 0;
#pragma unroll
        for (int e = 1; e < NEXP; ++e) if (lg[e] > lg[i0]) i0 = e;
        int i1 = (i0 == 0) ? 1 : 0;
#pragma unroll
        for (int e = 0; e < NEXP; ++e) {
            if (e == i0) continue;
            if (lg[e] > lg[i1]) i1 = e;
        }
        cOut[t] = 0.5f * (hrow[i0] + hrow[i1]);
    }
}

__global__ void colsum_k(const float* __restrict__ Wout, float* __restrict__ cs)
{
    int o = blockIdx.x;
    int tid = threadIdx.x;
    float s = 0.f;
    for (int d = tid; d < DMODEL; d += 256) s += Wout[(size_t)d * NOUT + o];
    __shared__ float red[8];
#pragma unroll
    for (int off = 16; off; off >>= 1) s += __shfl_xor_sync(0xffffffffu, s, off);
    if ((tid & 31) == 0) red[tid >> 5] = s;
    __syncthreads();
    if (tid < 32) {
        float t = (tid < 8) ? red[tid] : 0.f;
#pragma unroll
        for (int off = 4; off; off >>= 1) t += __shfl_xor_sync(0xffffffffu, t, off);
        if (tid == 0) cs[o] = t;
    }
}

__global__ void final_k(const float* __restrict__ c, const float* __restrict__ cs,
                        const float* __restrict__ bout, float* __restrict__ out)
{
    int t = blockIdx.x, o = threadIdx.x;
    out[(size_t)t * NOUT + o] = c[t] * cs[o] + bout[o];
}

// ---------------- launch ----------------
extern "C" void kernel_launch(void* const* d_in, const int* in_sizes, int n_in,
                              void* d_out, int out_size)
{
    const float* x    = (const float*)d_in[0];
    const float* Wi   = (const float*)d_in[1];
    const float* bi   = (const float*)d_in[2];
    const float* ln1w = (const float*)d_in[3];
    const float* Wq   = (const float*)d_in[4];
    const float* Wk   = (const float*)d_in[5];
    const float* Wv   = (const float*)d_in[6];
    const float* Wo   = (const float*)d_in[7];
    const float* ln2w = (const float*)d_in[8];
    const float* Wg   = (const float*)d_in[9];
    const float* Wu   = (const float*)d_in[10];
    const float* Wd   = (const float*)d_in[11];
    const float* Wr   = (const float*)d_in[12];
    const float* br   = (const float*)d_in[13];
    const float* Wout = (const float*)d_in[14];
    const float* bout = (const float*)d_in[15];
    float* out = (float*)d_out;

    float *h0, *a, *q, *k, *v, *attn, *h, *sc, *gb, *ub, *c, *cs;
    __nv_bfloat16 *Ahi, *Alo, *Bhi, *Blo;
    cudaGetSymbolAddress((void**)&h0,   g_h0);
    cudaGetSymbolAddress((void**)&a,    g_a);
    cudaGetSymbolAddress((void**)&q,    g_q);
    cudaGetSymbolAddress((void**)&k,    g_k);
    cudaGetSymbolAddress((void**)&v,    g_v);
    cudaGetSymbolAddress((void**)&attn, g_attn);
    cudaGetSymbolAddress((void**)&h,    g_h);
    cudaGetSymbolAddress((void**)&sc,   g_sc);
    cudaGetSymbolAddress((void**)&gb,   g_gbuf);
    cudaGetSymbolAddress((void**)&ub,   g_ubuf);
    cudaGetSymbolAddress((void**)&c,    g_c);
    cudaGetSymbolAddress((void**)&cs,   g_cs);
    cudaGetSymbolAddress((void**)&Ahi,  g_Ahi);
    cudaGetSymbolAddress((void**)&Alo,  g_Alo);
    cudaGetSymbolAddress((void**)&Bhi,  g_Bhi);
    cudaGetSymbolAddress((void**)&Blo,  g_Blo);

    static bool attr_set = false;
    if (!attr_set) {
        cudaFuncSetAttribute(gemm_bf3, cudaFuncAttributeMaxDynamicSharedMemorySize,
                             NSTAGE * STAGE_E * 2);
        attr_set = true;
    }
    const size_t GSM = NSTAGE * STAGE_E * 2;

    // 1. h0 = x @ Wi + bi
    cvt_split<<<(TOK * DIN) / 1024, 256>>>(x, Ahi, Alo);
    cvt_wt_t<<<dim3(DMODEL / 32, DIN / 32), dim3(32, 8)>>>(Wi, Bhi, Blo, DIN, DMODEL);
    gemm_bf3<<<dim3(32, 32), 256, GSM>>>(Ahi, Alo, DIN, Bhi, Blo, DIN,
                                         h0, DMODEL, DIN, bi, nullptr);
    // 2. a = rmsnorm(h0, ln1)
    rmsnorm_k<<<TOK, 256>>>(h0, ln1w, a);
    // 3. q,k,v = a @ {Wq,Wk,Wv}
    cvt_split<<<((size_t)TOK * DMODEL) / 1024, 256>>>(a, Ahi, Alo);
    cvt_wt_t<<<dim3(DMODEL / 32, DMODEL / 32), dim3(32, 8)>>>(Wq, Bhi, Blo, DMODEL, DMODEL);
    gemm_bf3<<<dim3(32, 32), 256, GSM>>>(Ahi, Alo, DMODEL, Bhi, Blo, DMODEL,
                                         q, DMODEL, DMODEL, nullptr, nullptr);
    cvt_wt_t<<<dim3(DMODEL / 32, DMODEL / 32), dim3(32, 8)>>>(Wk, Bhi, Blo, DMODEL, DMODEL);
    gemm_bf3<<<dim3(32, 32), 256, GSM>>>(Ahi, Alo, DMODEL, Bhi, Blo, DMODEL,
                                         k, DMODEL, DMODEL, nullptr, nullptr);
    cvt_wt_t<<<dim3(DMODEL / 32, DMODEL / 32), dim3(32, 8)>>>(Wv, Bhi, Blo, DMODEL, DMODEL);
    gemm_bf3<<<dim3(32, 32), 256, GSM>>>(Ahi, Alo, DMODEL, Bhi, Blo, DMODEL,
                                         v, DMODEL, DMODEL, nullptr, nullptr);
    // 4-6. attention (fp32 path)
    scores_nt<<<dim3(8, 8, 128), 256>>>(q, k, sc);
    softmax_k<<<128 * SEQ, 256>>>(sc);
    sgemm_nn<<<dim3(1, 8, 128), 256>>>(
        sc, SEQ, (size_t)32 * SEQ * SEQ, (size_t)SEQ * SEQ,
        v, DMODEL, (size_t)SEQ * DMODEL, (size_t)DHEAD,
        attn, DMODEL, (size_t)SEQ * DMODEL, (size_t)DHEAD,
        SEQ, 5, nullptr, nullptr);
    // 7. h = h0 + attn @ Wo
    cvt_split<<<((size_t)TOK * DMODEL) / 1024, 256>>>(attn, Ahi, Alo);
    cvt_wt_t<<<dim3(DMODEL / 32, DMODEL / 32), dim3(32, 8)>>>(Wo, Bhi, Blo, DMODEL, DMODEL);
    gemm_bf3<<<dim3(32, 32), 256, GSM>>>(Ahi, Alo, DMODEL, Bhi, Blo, DMODEL,
                                         h, DMODEL, DMODEL, nullptr, h0);
    // 8. m = rmsnorm(h, ln2)
    rmsnorm_k<<<TOK, 256>>>(h, ln2w, a);
    // 9. g = m @ Wg ; u = m @ Wu
    cvt_split<<<((size_t)TOK * DMODEL) / 1024, 256>>>(a, Ahi, Alo);
    cvt_wt_t<<<dim3(FFN / 32, DMODEL / 32), dim3(32, 8)>>>(Wg, Bhi, Blo, DMODEL, FFN);
    gemm_bf3<<<dim3(128, 32), 256, GSM>>>(Ahi, Alo, DMODEL, Bhi, Blo, DMODEL,
                                          gb, FFN, DMODEL, nullptr, nullptr);
    cvt_wt_t<<<dim3(FFN / 32, DMODEL / 32), dim3(32, 8)>>>(Wu, Bhi, Blo, DMODEL, FFN);
    gemm_bf3<<<dim3(128, 32), 256, GSM>>>(Ahi, Alo, DMODEL, Bhi, Blo, DMODEL,
                                          ub, FFN, DMODEL, nullptr, nullptr);
    // 10. t = silu(g) * u
    silumul_k<<<((size_t)TOK * FFN) / (256 * 4), 256>>>(gb, ub);
    // 11. h = h + t @ Wd
    cvt_split<<<((size_t)TOK * FFN) / 1024, 256>>>(gb, Ahi, Alo);
    cvt_wt_t<<<dim3(DMODEL / 32, FFN / 32), dim3(32, 8)>>>(Wd, Bhi, Blo, FFN, DMODEL);
    gemm_bf3<<<dim3(32, 32), 256, GSM>>>(Ahi, Alo, FFN, Bhi, Blo, FFN,
                                         h, DMODEL, FFN, nullptr, h);
    // 12-13. router + output
    router_k<<<TOK, 128>>>(h, Wr, br, c);
    colsum_k<<<NOUT, 256>>>(Wout, cs);
    final_k<<<TOK, NOUT>>>(c, cs, bout, out);
}

// round 14
// speedup vs baseline: 1.2295x; 1.1682x over previous
#include <cuda_runtime.h>
#include <cuda_bf16.h>
#include <math.h>
#include <float.h>

// ---------------- problem constants ----------------
#define TOK   4096
#define DMODEL 4096
#define DIN   512
#define FFN   16384
#define SEQ   1024
#define NHEAD 32
#define DHEAD 128
#define NEXP  8
#define NOUT  256

// ---------------- scratch ----------------
__device__ float g_h0  [(size_t)TOK * DMODEL];
__device__ float g_a   [(size_t)TOK * DMODEL];
__device__ float g_q   [(size_t)TOK * DMODEL];
__device__ float g_k   [(size_t)TOK * DMODEL];
__device__ float g_v   [(size_t)TOK * DMODEL];
__device__ float g_attn[(size_t)TOK * DMODEL];
__device__ float g_h   [(size_t)TOK * DMODEL];
__device__ float g_sc  [(size_t)128 * SEQ * SEQ];          // fp32 scores
__device__ float g_gbuf[(size_t)TOK * FFN];
__device__ float g_ubuf[(size_t)TOK * FFN];
__device__ float g_c   [TOK];
__device__ float g_cs  [NOUT];
__device__ __nv_bfloat16 g_Ahi[(size_t)TOK * FFN];
__device__ __nv_bfloat16 g_Alo[(size_t)TOK * FFN];
__device__ __nv_bfloat16 g_Bhi[(size_t)FFN * DMODEL];
__device__ __nv_bfloat16 g_Blo[(size_t)FFN * DMODEL];
__device__ __nv_bfloat16 g_phi[(size_t)128 * SEQ * SEQ];   // softmax p hi
__device__ __nv_bfloat16 g_plo[(size_t)128 * SEQ * SEQ];   // softmax p lo
__device__ __nv_bfloat16 g_vthi[(size_t)128 * DHEAD * SEQ];// v^T per head hi
__device__ __nv_bfloat16 g_vtlo[(size_t)128 * DHEAD * SEQ];// v^T per head lo

// ---------------- PTX helpers ----------------
__device__ __forceinline__ void mma16816(float* c, const unsigned* a,
                                         unsigned b0, unsigned b1)
{
    asm volatile(
        "mma.sync.aligned.m16n8k16.row.col.f32.bf16.bf16.f32 "
        "{%0,%1,%2,%3},{%4,%5,%6,%7},{%8,%9},{%0,%1,%2,%3};\n"
        : "+f"(c[0]), "+f"(c[1]), "+f"(c[2]), "+f"(c[3])
        : "r"(a[0]), "r"(a[1]), "r"(a[2]), "r"(a[3]), "r"(b0), "r"(b1));
}

__device__ __forceinline__ void cpa16(void* smem_dst, const void* gsrc)
{
    unsigned sa = (unsigned)__cvta_generic_to_shared(smem_dst);
    asm volatile("cp.async.cg.shared.global [%0], [%1], 16;\n" :: "r"(sa), "l"(gsrc));
}

__device__ __forceinline__ void ldm_x4(unsigned* r, const __nv_bfloat16* p)
{
    unsigned sa = (unsigned)__cvta_generic_to_shared(p);
    asm volatile("ldmatrix.sync.aligned.m8n8.x4.shared.b16 {%0,%1,%2,%3}, [%4];\n"
                 : "=r"(r[0]), "=r"(r[1]), "=r"(r[2]), "=r"(r[3]) : "r"(sa));
}

// ================= main bf16x3 GEMM: 256x128 tile, 64x64 warp tile =================
#define TILE_A2  10240     // 256 rows * 40
#define TILE_B2  5120      // 128 rows * 40
#define STAGE_E2 30720     // 2*TILE_A2 + 2*TILE_B2
#define NSTAGE   3
#define GSM2     (NSTAGE * STAGE_E2 * 2)   // 184320 bytes

__global__ __launch_bounds__(256, 1)
void gemm_bf3(const __nv_bfloat16* __restrict__ A_hi, const __nv_bfloat16* __restrict__ A_lo, int lda,
              const __nv_bfloat16* __restrict__ Bt_hi, const __nv_bfloat16* __restrict__ Bt_lo, int ldb,
              float* __restrict__ C, int ldc, int K,
              const float* __restrict__ bias, const float* __restrict__ resid)
{
    extern __shared__ __nv_bfloat16 sm[];

    const int m0 = blockIdx.y * 256;
    const int n0 = blockIdx.x * 128;
    const int tid = threadIdx.x;
    const int lane = tid & 31;
    const int wid = tid >> 5;
    const int warp_m = (wid >> 1) * 64;     // 0,64,128,192
    const int warp_n = (wid & 1) * 64;      // 0,64

    const int chunk = tid & 3;              // 16B chunk within 64B row
    const int arow  = tid >> 2;             // 0..63

    float acc[4][8][4];
#pragma unroll
    for (int i = 0; i < 4; ++i)
#pragma unroll
        for (int j = 0; j < 8; ++j)
#pragma unroll
            for (int t = 0; t < 4; ++t) acc[i][j][t] = 0.f;

    const int nit = K >> 5;

    auto issue = [&](int st, int k0) {
        __nv_bfloat16* Ah = sm + st * STAGE_E2;
        __nv_bfloat16* Al = Ah + TILE_A2;
        __nv_bfloat16* Bh = Ah + 2 * TILE_A2;
        __nv_bfloat16* Bl = Bh + TILE_B2;
#pragma unroll
        for (int p = 0; p < 4; ++p) {
            int r = arow + p * 64;
            int so = r * 40 + chunk * 8;
            cpa16(&Ah[so], A_hi + (size_t)(m0 + r) * lda + k0 + chunk * 8);
            cpa16(&Al[so], A_lo + (size_t)(m0 + r) * lda + k0 + chunk * 8);
        }
#pragma unroll
        for (int p = 0; p < 2; ++p) {
            int r = arow + p * 64;
            int so = r * 40 + chunk * 8;
            cpa16(&Bh[so], Bt_hi + (size_t)(n0 + r) * ldb + k0 + chunk * 8);
            cpa16(&Bl[so], Bt_lo + (size_t)(n0 + r) * ldb + k0 + chunk * 8);
        }
    };

    issue(0, 0);
    asm volatile("cp.async.commit_group;\n");
    if (nit > 1) issue(1, 32);
    asm volatile("cp.async.commit_group;\n");

    const int a_r = (lane & 15);
    const int a_c = (lane >> 4) * 8;
    const int b_r = (lane & 7) + ((lane >> 4) << 3);
    const int b_c = ((lane >> 3) & 1) * 8;

    for (int it = 0; it < nit; ++it) {
        asm volatile("cp.async.wait_group 1;\n");
        __syncthreads();

        if (it + 2 < nit) issue((it + 2) % NSTAGE, (it + 2) * 32);
        asm volatile("cp.async.commit_group;\n");

        const __nv_bfloat16* Ah = sm + (it % NSTAGE) * STAGE_E2;
        const __nv_bfloat16* Al = Ah + TILE_A2;
        const __nv_bfloat16* Bh = Ah + 2 * TILE_A2;
        const __nv_bfloat16* Bl = Bh + TILE_B2;

#pragma unroll
        for (int kk = 0; kk < 32; kk += 16) {
            unsigned ah[4][4], al[4][4];
#pragma unroll
            for (int i = 0; i < 4; ++i) {
                ldm_x4(ah[i], Ah + (warp_m + i * 16 + a_r) * 40 + kk + a_c);
                ldm_x4(al[i], Al + (warp_m + i * 16 + a_r) * 40 + kk + a_c);
            }
            unsigned bh[4][4], bl[4][4];
#pragma unroll
            for (int jj = 0; jj < 4; ++jj) {
                ldm_x4(bh[jj], Bh + (warp_n + jj * 16 + b_r) * 40 + kk + b_c);
                ldm_x4(bl[jj], Bl + (warp_n + jj * 16 + b_r) * 40 + kk + b_c);
            }
#pragma unroll
            for (int j = 0; j < 8; ++j) {
                int jj = j >> 1, s = (j & 1) * 2;
                unsigned bh0 = bh[jj][s], bh1 = bh[jj][s + 1];
                unsigned bl0 = bl[jj][s], bl1 = bl[jj][s + 1];
#pragma unroll
                for (int i = 0; i < 4; ++i) {
                    mma16816(acc[i][j], ah[i], bh0, bh1);
                    mma16816(acc[i][j], al[i], bh0, bh1);
                    mma16816(acc[i][j], ah[i], bl0, bl1);
                }
            }
        }
        __syncthreads();
    }

#pragma unroll
    for (int i = 0; i < 4; ++i) {
        int r0 = m0 + warp_m + i * 16 + (lane >> 2);
#pragma unroll
        for (int j = 0; j < 8; ++j) {
            int cc = n0 + warp_n + j * 8 + (lane & 3) * 2;
            float2 v0 = make_float2(acc[i][j][0], acc[i][j][1]);
            float2 v1 = make_float2(acc[i][j][2], acc[i][j][3]);
            if (bias) {
                float b0 = bias[cc], b1 = bias[cc + 1];
                v0.x += b0; v0.y += b1; v1.x += b0; v1.y += b1;
            }
            if (resid) {
                float2 r0v = *(const float2*)&resid[(size_t)r0 * ldc + cc];
                float2 r1v = *(const float2*)&resid[(size_t)(r0 + 8) * ldc + cc];
                v0.x += r0v.x; v0.y += r0v.y; v1.x += r1v.x; v1.y += r1v.y;
            }
            *(float2*)&C[(size_t)r0 * ldc + cc] = v0;
            *(float2*)&C[(size_t)(r0 + 8) * ldc + cc] = v1;
        }
    }
}

// ================= attention TC kernels: 128x128 tile, 64x32 warp tile =================
#define TILE_E  5120
#define STAGE_E 20480
#define GSM1    (NSTAGE * STAGE_E * 2)     // 122880 bytes

// scores = causal( Q K^T / sqrt(dh) )  per z=(b*32+h), bf16x3
__global__ __launch_bounds__(256, 1)
void scores_tc(const __nv_bfloat16* __restrict__ Qhi, const __nv_bfloat16* __restrict__ Qlo,
               const __nv_bfloat16* __restrict__ Khi, const __nv_bfloat16* __restrict__ Klo,
               float* __restrict__ Sc)
{
    const int z = blockIdx.z;
    const int b = z >> 5, h = z & 31;
    const int m0 = blockIdx.y * 128;
    const int n0 = blockIdx.x * 128;
    const int tid = threadIdx.x;

    float* C = Sc + (size_t)z * SEQ * SEQ;

    if (n0 > m0) {   // fully masked tile
        const float NEG = -3.402823466e+38f;
        float4 neg = make_float4(NEG, NEG, NEG, NEG);
        for (int i = tid; i < 128 * 32; i += 256) {
            int r = i >> 5, c = (i & 31) * 4;
            *(float4*)&C[(size_t)(m0 + r) * SEQ + n0 + c] = neg;
        }
        return;
    }

    extern __shared__ __nv_bfloat16 sm[];
    const size_t base_off = (size_t)b * SEQ * DMODEL + (size_t)h * DHEAD;
    const __nv_bfloat16* Ahg = Qhi + base_off;
    const __nv_bfloat16* Alg = Qlo + base_off;
    const __nv_bfloat16* Bhg = Khi + base_off;
    const __nv_bfloat16* Blg = Klo + base_off;

    const int lane = tid & 31;
    const int wid = tid >> 5;
    const int warp_m = (wid >> 2) * 64;
    const int warp_n = (wid & 3) * 32;
    const int row  = tid >> 1;
    const int half = tid & 1;

    float acc[4][4][4];
#pragma unroll
    for (int i = 0; i < 4; ++i)
#pragma unroll
        for (int j = 0; j < 4; ++j)
#pragma unroll
            for (int t = 0; t < 4; ++t) acc[i][j][t] = 0.f;

    const int nit = DHEAD >> 5;  // 4

    auto issue = [&](int st, int k0) {
        __nv_bfloat16* Ah = sm + st * STAGE_E;
        __nv_bfloat16* Al = Ah + TILE_E;
        __nv_bfloat16* Bh = Ah + 2 * TILE_E;
        __nv_bfloat16* Bl = Ah + 3 * TILE_E;
        int so = row * 40 + half * 16;
        const __nv_bfloat16* gA = Ahg + (size_t)(m0 + row) * DMODEL + k0 + half * 16;
        const __nv_bfloat16* gAl2 = Alg + (size_t)(m0 + row) * DMODEL + k0 + half * 16;
        const __nv_bfloat16* gB = Bhg + (size_t)(n0 + row) * DMODEL + k0 + half * 16;
        const __nv_bfloat16* gBl2 = Blg + (size_t)(n0 + row) * DMODEL + k0 + half * 16;
        cpa16(&Ah[so], gA);   cpa16(&Ah[so + 8], gA + 8);
        cpa16(&Al[so], gAl2); cpa16(&Al[so + 8], gAl2 + 8);
        cpa16(&Bh[so], gB);   cpa16(&Bh[so + 8], gB + 8);
        cpa16(&Bl[so], gBl2); cpa16(&Bl[so + 8], gBl2 + 8);
    };

    issue(0, 0);
    asm volatile("cp.async.commit_group;\n");
    issue(1, 32);
    asm volatile("cp.async.commit_group;\n");

    const int a_r = (lane & 15);
    const int a_c = (lane >> 4) * 8;
    const int b_r = (lane & 7) + ((lane >> 4) << 3);
    const int b_c = ((lane >> 3) & 1) * 8;

    for (int it = 0; it < nit; ++it) {
        asm volatile("cp.async.wait_group 1;\n");
        __syncthreads();
        if (it + 2 < nit) issue((it + 2) % NSTAGE, (it + 2) * 32);
        asm volatile("cp.async.commit_group;\n");

        const __nv_bfloat16* Ah = sm + (it % NSTAGE) * STAGE_E;
        const __nv_bfloat16* Al = Ah + TILE_E;
        const __nv_bfloat16* Bh = Ah + 2 * TILE_E;
        const __nv_bfloat16* Bl = Ah + 3 * TILE_E;

#pragma unroll
        for (int kk = 0; kk < 32; kk += 16) {
            unsigned ah[4][4], al[4][4];
#pragma unroll
            for (int i = 0; i < 4; ++i) {
                ldm_x4(ah[i], Ah + (warp_m + i * 16 + a_r) * 40 + kk + a_c);
                ldm_x4(al[i], Al + (warp_m + i * 16 + a_r) * 40 + kk + a_c);
            }
            unsigned bh[2][4], bl[2][4];
#pragma unroll
            for (int jj = 0; jj < 2; ++jj) {
                ldm_x4(bh[jj], Bh + (warp_n + jj * 16 + b_r) * 40 + kk + b_c);
                ldm_x4(bl[jj], Bl + (warp_n + jj * 16 + b_r) * 40 + kk + b_c);
            }
#pragma unroll
            for (int j = 0; j < 4; ++j) {
                unsigned bh0 = bh[j >> 1][(j & 1) * 2], bh1 = bh[j >> 1][(j & 1) * 2 + 1];
                unsigned bl0 = bl[j >> 1][(j & 1) * 2], bl1 = bl[j >> 1][(j & 1) * 2 + 1];
#pragma unroll
                for (int i = 0; i < 4; ++i) {
                    mma16816(acc[i][j], ah[i], bh0, bh1);
                    mma16816(acc[i][j], al[i], bh0, bh1);
                    mma16816(acc[i][j], ah[i], bl0, bl1);
                }
            }
        }
        __syncthreads();
    }

    const float scale = 0.08838834764831845f;
    const float NEG = -3.402823466e+38f;
#pragma unroll
    for (int i = 0; i < 4; ++i) {
        int r0 = m0 + warp_m + i * 16 + (lane >> 2);
#pragma unroll
        for (int j = 0; j < 4; ++j) {
            int cc = n0 + warp_n + j * 8 + (lane & 3) * 2;
            float2 v0, v1;
            v0.x = (cc     <= r0)     ? acc[i][j][0] * scale : NEG;
            v0.y = (cc + 1 <= r0)     ? acc[i][j][1] * scale : NEG;
            v1.x = (cc     <= r0 + 8) ? acc[i][j][2] * scale : NEG;
            v1.y = (cc + 1 <= r0 + 8) ? acc[i][j][3] * scale : NEG;
            *(float2*)&C[(size_t)r0 * SEQ + cc] = v0;
            *(float2*)&C[(size_t)(r0 + 8) * SEQ + cc] = v1;
        }
    }
}

// attn = P @ V per z, bf16x3, with causal K-limit
__global__ __launch_bounds__(256, 1)
void pv_tc(const __nv_bfloat16* __restrict__ Phi, const __nv_bfloat16* __restrict__ Plo,
           const __nv_bfloat16* __restrict__ Vthi, const __nv_bfloat16* __restrict__ Vtlo,
           float* __restrict__ Attn)
{
    const int z = blockIdx.z;
    const int b = z >> 5, h = z & 31;
    const int m0 = blockIdx.y * 128;
    const int tid = threadIdx.x;

    extern __shared__ __nv_bfloat16 sm[];
    const __nv_bfloat16* Ahg = Phi + (size_t)z * SEQ * SEQ;
    const __nv_bfloat16* Alg = Plo + (size_t)z * SEQ * SEQ;
    const __nv_bfloat16* Bhg = Vthi + (size_t)z * DHEAD * SEQ;
    const __nv_bfloat16* Blg = Vtlo + (size_t)z * DHEAD * SEQ;
    float* C = Attn + (size_t)b * SEQ * DMODEL + (size_t)h * DHEAD;

    const int lane = tid & 31;
    const int wid = tid >> 5;
    const int warp_m = (wid >> 2) * 64;
    const int warp_n = (wid & 3) * 32;
    const int row  = tid >> 1;
    const int half = tid & 1;

    float acc[4][4][4];
#pragma unroll
    for (int i = 0; i < 4; ++i)
#pragma unroll
        for (int j = 0; j < 4; ++j)
#pragma unroll
            for (int t = 0; t < 4; ++t) acc[i][j][t] = 0.f;

    const int nit = (m0 + 128) >> 5;   // causal: keys < m0+128

    auto issue = [&](int st, int k0) {
        __nv_bfloat16* Ah = sm + st * STAGE_E;
        __nv_bfloat16* Al = Ah + TILE_E;
        __nv_bfloat16* Bh = Ah + 2 * TILE_E;
        __nv_bfloat16* Bl = Ah + 3 * TILE_E;
        int so = row * 40 + half * 16;
        const __nv_bfloat16* gA = Ahg + (size_t)(m0 + row) * SEQ + k0 + half * 16;
        const __nv_bfloat16* gAl2 = Alg + (size_t)(m0 + row) * SEQ + k0 + half * 16;
        const __nv_bfloat16* gB = Bhg + (size_t)row * SEQ + k0 + half * 16;
        const __nv_bfloat16* gBl2 = Blg + (size_t)row * SEQ + k0 + half * 16;
        cpa16(&Ah[so], gA);   cpa16(&Ah[so + 8], gA + 8);
        cpa16(&Al[so], gAl2); cpa16(&Al[so + 8], gAl2 + 8);
        cpa16(&Bh[so], gB);   cpa16(&Bh[so + 8], gB + 8);
        cpa16(&Bl[so], gBl2); cpa16(&Bl[so + 8], gBl2 + 8);
    };

    issue(0, 0);
    asm volatile("cp.async.commit_group;\n");
    issue(1, 32);
    asm volatile("cp.async.commit_group;\n");

    const int a_r = (lane & 15);
    const int a_c = (lane >> 4) * 8;
    const int b_r = (lane & 7) + ((lane >> 4) << 3);
    const int b_c = ((lane >> 3) & 1) * 8;

    for (int it = 0; it < nit; ++it) {
        asm volatile("cp.async.wait_group 1;\n");
        __syncthreads();
        if (it + 2 < nit) issue((it + 2) % NSTAGE, (it + 2) * 32);
        asm volatile("cp.async.commit_group;\n");

        const __nv_bfloat16* Ah = sm + (it % NSTAGE) * STAGE_E;
        const __nv_bfloat16* Al = Ah + TILE_E;
        const __nv_bfloat16* Bh = Ah + 2 * TILE_E;
        const __nv_bfloat16* Bl = Ah + 3 * TILE_E;

#pragma unroll
        for (int kk = 0; kk < 32; kk += 16) {
            unsigned ah[4][4], al[4][4];
#pragma unroll
            for (int i = 0; i < 4; ++i) {
                ldm_x4(ah[i], Ah + (warp_m + i * 16 + a_r) * 40 + kk + a_c);
                ldm_x4(al[i], Al + (warp_m + i * 16 + a_r) * 40 + kk + a_c);
            }
            unsigned bh[2][4], bl[2][4];
#pragma unroll
            for (int jj = 0; jj < 2; ++jj) {
                ldm_x4(bh[jj], Bh + (warp_n + jj * 16 + b_r) * 40 + kk + b_c);
                ldm_x4(bl[jj], Bl + (warp_n + jj * 16 + b_r) * 40 + kk + b_c);
            }
#pragma unroll
            for (int j = 0; j < 4; ++j) {
                unsigned bh0 = bh[j >> 1][(j & 1) * 2], bh1 = bh[j >> 1][(j & 1) * 2 + 1];
                unsigned bl0 = bl[j >> 1][(j & 1) * 2], bl1 = bl[j >> 1][(j & 1) * 2 + 1];
#pragma unroll
                for (int i = 0; i < 4; ++i) {
                    mma16816(acc[i][j], ah[i], bh0, bh1);
                    mma16816(acc[i][j], al[i], bh0, bh1);
                    mma16816(acc[i][j], ah[i], bl0, bl1);
                }
            }
        }
        __syncthreads();
    }

#pragma unroll
    for (int i = 0; i < 4; ++i) {
        int r0 = m0 + warp_m + i * 16 + (lane >> 2);
#pragma unroll
        for (int j = 0; j < 4; ++j) {
            int cc = warp_n + j * 8 + (lane & 3) * 2;
            *(float2*)&C[(size_t)r0 * DMODEL + cc] =
                make_float2(acc[i][j][0], acc[i][j][1]);
            *(float2*)&C[(size_t)(r0 + 8) * DMODEL + cc] =
                make_float2(acc[i][j][2], acc[i][j][3]);
        }
    }
}

// ---------------- softmax over rows; writes p as bf16 hi/lo ----------------
__global__ void softmax_pk(const float* __restrict__ Sc,
                           __nv_bfloat16* __restrict__ Phi, __nv_bfloat16* __restrict__ Plo)
{
    size_t base = (size_t)blockIdx.x * SEQ;
    int tid = threadIdx.x;
    float4 v = *(const float4*)&Sc[base + (size_t)tid * 4];

    float m = fmaxf(fmaxf(v.x, v.y), fmaxf(v.z, v.w));
    __shared__ float red[8];
#pragma unroll
    for (int o = 16; o; o >>= 1) m = fmaxf(m, __shfl_xor_sync(0xffffffffu, m, o));
    if ((tid & 31) == 0) red[tid >> 5] = m;
    __syncthreads();
    if (tid < 32) {
        float t = (tid < 8) ? red[tid] : -3.402823466e+38f;
#pragma unroll
        for (int o = 4; o; o >>= 1) t = fmaxf(t, __shfl_xor_sync(0xffffffffu, t, o));
        if (tid == 0) red[0] = t;
    }
    __syncthreads();
    m = red[0];

    float e0 = expf(v.x - m), e1 = expf(v.y - m), e2 = expf(v.z - m), e3 = expf(v.w - m);
    float s = e0 + e1 + e2 + e3;
    __syncthreads();
#pragma unroll
    for (int o = 16; o; o >>= 1) s += __shfl_xor_sync(0xffffffffu, s, o);
    if ((tid & 31) == 0) red[tid >> 5] = s;
    __syncthreads();
    if (tid < 32) {
        float t = (tid < 8) ? red[tid] : 0.f;
#pragma unroll
        for (int o = 4; o; o >>= 1) t += __shfl_xor_sync(0xffffffffu, t, o);
        if (tid == 0) red[0] = t;
    }
    __syncthreads();
    float inv = 1.f / red[0];

    float p0 = e0 * inv, p1 = e1 * inv, p2 = e2 * inv, p3 = e3 * inv;
    __nv_bfloat16 h0 = __float2bfloat16_rn(p0), h1 = __float2bfloat16_rn(p1);
    __nv_bfloat16 h2 = __float2bfloat16_rn(p2), h3 = __float2bfloat16_rn(p3);
    __nv_bfloat162 ph;
    ph.x = h0; ph.y = h1; *(__nv_bfloat162*)&Phi[base + tid * 4]     = ph;
    ph.x = h2; ph.y = h3; *(__nv_bfloat162*)&Phi[base + tid * 4 + 2] = ph;
    ph.x = __float2bfloat16_rn(p0 - __bfloat162float(h0));
    ph.y = __float2bfloat16_rn(p1 - __bfloat162float(h1));
    *(__nv_bfloat162*)&Plo[base + tid * 4] = ph;
    ph.x = __float2bfloat16_rn(p2 - __bfloat162float(h2));
    ph.y = __float2bfloat16_rn(p3 - __bfloat162float(h3));
    *(__nv_bfloat162*)&Plo[base + tid * 4 + 2] = ph;
}

// ---------------- batched per-head transpose + split of V ----------------
// v[b*S+s][h*128+d] -> vt[z][d][s]  (z = b*32+h)
__global__ void vtrans_split(const float* __restrict__ V,
                             __nv_bfloat16* __restrict__ Vthi, __nv_bfloat16* __restrict__ Vtlo)
{
    __shared__ float t[32][33];
    int z = blockIdx.z;
    int b = z >> 5, h = z & 31;
    int s0 = blockIdx.y * 32;
    int d0 = blockIdx.x * 32;
    int tx = threadIdx.x, ty = threadIdx.y;
#pragma unroll
    for (int r = ty; r < 32; r += 8)
        t[r][tx] = V[(size_t)(b * SEQ + s0 + r) * DMODEL + h * DHEAD + d0 + tx];
    __syncthreads();
#pragma unroll
    for (int r = ty; r < 32; r += 8) {
        float val = t[tx][r];   // = v[s0+tx][d0+r]
        __nv_bfloat16 hi = __float2bfloat16_rn(val);
        __nv_bfloat16 lo = __float2bfloat16_rn(val - __bfloat162float(hi));
        size_t o = (size_t)z * DHEAD * SEQ + (size_t)(d0 + r) * SEQ + s0 + tx;
        Vthi[o] = hi; Vtlo[o] = lo;
    }
}

// ---------------- fp32 -> (hi,lo) bf16 split ----------------
__global__ void cvt_split(const float* __restrict__ X,
                          __nv_bfloat16* __restrict__ hi, __nv_bfloat16* __restrict__ lo)
{
    size_t i = ((size_t)blockIdx.x * 256 + threadIdx.x) * 4;
    float4 v = *(const float4*)&X[i];
    __nv_bfloat16 h0 = __float2bfloat16_rn(v.x);
    __nv_bfloat16 h1 = __float2bfloat16_rn(v.y);
    __nv_bfloat16 h2 = __float2bfloat16_rn(v.z);
    __nv_bfloat16 h3 = __float2bfloat16_rn(v.w);
    __nv_bfloat16 l0 = __float2bfloat16_rn(v.x - __bfloat162float(h0));
    __nv_bfloat16 l1 = __float2bfloat16_rn(v.y - __bfloat162float(h1));
    __nv_bfloat16 l2 = __float2bfloat16_rn(v.z - __bfloat162float(h2));
    __nv_bfloat16 l3 = __float2bfloat16_rn(v.w - __bfloat162float(h3));
    __nv_bfloat162 p;
    p.x = h0; p.y = h1; *(__nv_bfloat162*)&hi[i]     = p;
    p.x = h2; p.y = h3; *(__nv_bfloat162*)&hi[i + 2] = p;
    p.x = l0; p.y = l1; *(__nv_bfloat162*)&lo[i]     = p;
    p.x = l2; p.y = l3; *(__nv_bfloat162*)&lo[i + 2] = p;
}

// ---------------- weight [K][N] -> transposed (hi,lo) bf16 [N][K] ----------------
__global__ void cvt_wt_t(const float* __restrict__ W,
                         __nv_bfloat16* __restrict__ bhi, __nv_bfloat16* __restrict__ blo,
                         int K, int N)
{
    __shared__ float t[32][33];
    int n0 = blockIdx.x * 32, k0 = blockIdx.y * 32;
    int tx = threadIdx.x, ty = threadIdx.y;
#pragma unroll
    for (int r = ty; r < 32; r += 8)
        t[r][tx] = W[(size_t)(k0 + r) * N + n0 + tx];
    __syncthreads();
#pragma unroll
    for (int r = ty; r < 32; r += 8) {
        float v = t[tx][r];
        __nv_bfloat16 h = __float2bfloat16_rn(v);
        __nv_bfloat16 l = __float2bfloat16_rn(v - __bfloat162float(h));
        size_t o = (size_t)(n0 + r) * K + k0 + tx;
        bhi[o] = h; blo[o] = l;
    }
}

// ---------------- elementwise / reduction helpers ----------------
__global__ void rmsnorm_k(const float* __restrict__ X, const float* __restrict__ W,
                          float* __restrict__ Y)
{
    size_t base = (size_t)blockIdx.x * DMODEL;
    int tid = threadIdx.x;
    float4 v[4];
    float ss = 0.f;
#pragma unroll
    for (int u = 0; u < 4; ++u) {
        v[u] = *(const float4*)&X[base + (size_t)tid * 4 + (size_t)u * 1024];
        ss += v[u].x * v[u].x + v[u].y * v[u].y + v[u].z * v[u].z + v[u].w * v[u].w;
    }
    __shared__ float red[8];
#pragma unroll
    for (int o = 16; o; o >>= 1) ss += __shfl_xor_sync(0xffffffffu, ss, o);
    if ((tid & 31) == 0) red[tid >> 5] = ss;
    __syncthreads();
    if (tid < 32) {
        float t = (tid < 8) ? red[tid] : 0.f;
#pragma unroll
        for (int o = 4; o; o >>= 1) t += __shfl_xor_sync(0xffffffffu, t, o);
        if (tid == 0) red[0] = t;
    }
    __syncthreads();
    float r = rsqrtf(red[0] / (float)DMODEL + 1e-6f);
#pragma unroll
    for (int u = 0; u < 4; ++u) {
        float4 w4 = *(const float4*)&W[(size_t)tid * 4 + (size_t)u * 1024];
        float4 o;
        o.x = v[u].x * r * w4.x; o.y = v[u].y * r * w4.y;
        o.z = v[u].z * r * w4.z; o.w = v[u].w * r * w4.w;
        *(float4*)&Y[base + (size_t)tid * 4 + (size_t)u * 1024] = o;
    }
}

__global__ void silumul_k(float* __restrict__ G, const float* __restrict__ U)
{
    size_t i = ((size_t)blockIdx.x * blockDim.x + threadIdx.x) * 4;
    float4 g = *(float4*)&G[i];
    float4 u = *(const float4*)&U[i];
    g.x = g.x / (1.f + expf(-g.x)) * u.x;
    g.y = g.y / (1.f + expf(-g.y)) * u.y;
    g.z = g.z / (1.f + expf(-g.z)) * u.z;
    g.w = g.w / (1.f + expf(-g.w)) * u.w;
    *(float4*)&G[i] = g;
}

__global__ void router_k(const float* __restrict__ H, const float* __restrict__ Wr,
                         const float* __restrict__ br, float* __restrict__ cOut)
{
    int t = blockIdx.x;
    int tid = threadIdx.x;
    float p[NEXP];
#pragma unroll
    for (int e = 0; e < NEXP; ++e) p[e] = 0.f;
    const float* hrow = H + (size_t)t * DMODEL;
    for (int d = tid; d < DMODEL; d += 128) {
        float hv = hrow[d];
        const float* wr = &Wr[(size_t)d * NEXP];
#pragma unroll
        for (int e = 0; e < NEXP; ++e) p[e] = fmaf(hv, wr[e], p[e]);
    }
    __shared__ float red[NEXP * 128];
#pragma unroll
    for (int e = 0; e < NEXP; ++e) red[e * 128 + tid] = p[e];
    __syncthreads();
    for (int off = 64; off > 0; off >>= 1) {
        if (tid < off) {
#pragma unroll
            for (int e = 0; e < NEXP; ++e)
                red[e * 128 + tid] += red[e * 128 + tid + off];
        }
        __syncthreads();
    }
    if (tid == 0) {
        float lg[NEXP];
#pragma unroll
        for (int e = 0; e < NEXP; ++e) lg[e] = red[e * 128] + br[e];
        int i0 = 0;
#pragma unroll
        for (int e = 1; e < NEXP; ++e) if (lg[e] > lg[i0]) i0 = e;
        int i1 = (i0 == 0) ? 1 : 0;
#pragma unroll
        for (int e = 0; e < NEXP; ++e) {
            if (e == i0) continue;
            if (lg[e] > lg[i1]) i1 = e;
        }
        cOut[t] = 0.5f * (hrow[i0] + hrow[i1]);
    }
}

__global__ void colsum_k(const float* __restrict__ Wout, float* __restrict__ cs)
{
    int o = blockIdx.x;
    int tid = threadIdx.x;
    float s = 0.f;
    for (int d = tid; d < DMODEL; d += 256) s += Wout[(size_t)d * NOUT + o];
    __shared__ float red[8];
#pragma unroll
    for (int off = 16; off; off >>= 1) s += __shfl_xor_sync(0xffffffffu, s, off);
    if ((tid & 31) == 0) red[tid >> 5] = s;
    __syncthreads();
    if (tid < 32) {
        float t = (tid < 8) ? red[tid] : 0.f;
#pragma unroll
        for (int off = 4; off; off >>= 1) t += __shfl_xor_sync(0xffffffffu, t, off);
        if (tid == 0) cs[o] = t;
    }
}

__global__ void final_k(const float* __restrict__ c, const float* __restrict__ cs,
                        const float* __restrict__ bout, float* __restrict__ out)
{
    int t = blockIdx.x, o = threadIdx.x;
    out[(size_t)t * NOUT + o] = c[t] * cs[o] + bout[o];
}

// ---------------- launch ----------------
extern "C" void kernel_launch(void* const* d_in, const int* in_sizes, int n_in,
                              void* d_out, int out_size)
{
    const float* x    = (const float*)d_in[0];
    const float* Wi   = (const float*)d_in[1];
    const float* bi   = (const float*)d_in[2];
    const float* ln1w = (const float*)d_in[3];
    const float* Wq   = (const float*)d_in[4];
    const float* Wk   = (const float*)d_in[5];
    const float* Wv   = (const float*)d_in[6];
    const float* Wo   = (const float*)d_in[7];
    const float* ln2w = (const float*)d_in[8];
    const float* Wg   = (const float*)d_in[9];
    const float* Wu   = (const float*)d_in[10];
    const float* Wd   = (const float*)d_in[11];
    const float* Wr   = (const float*)d_in[12];
    const float* br   = (const float*)d_in[13];
    const float* Wout = (const float*)d_in[14];
    const float* bout = (const float*)d_in[15];
    float* out = (float*)d_out;

    float *h0, *a, *q, *k, *v, *attn, *h, *sc, *gb, *ub, *c, *cs;
    __nv_bfloat16 *Ahi, *Alo, *Bhi, *Blo, *phi, *plo, *vthi, *vtlo;
    cudaGetSymbolAddress((void**)&h0,   g_h0);
    cudaGetSymbolAddress((void**)&a,    g_a);
    cudaGetSymbolAddress((void**)&q,    g_q);
    cudaGetSymbolAddress((void**)&k,    g_k);
    cudaGetSymbolAddress((void**)&v,    g_v);
    cudaGetSymbolAddress((void**)&attn, g_attn);
    cudaGetSymbolAddress((void**)&h,    g_h);
    cudaGetSymbolAddress((void**)&sc,   g_sc);
    cudaGetSymbolAddress((void**)&gb,   g_gbuf);
    cudaGetSymbolAddress((void**)&ub,   g_ubuf);
    cudaGetSymbolAddress((void**)&c,    g_c);
    cudaGetSymbolAddress((void**)&cs,   g_cs);
    cudaGetSymbolAddress((void**)&Ahi,  g_Ahi);
    cudaGetSymbolAddress((void**)&Alo,  g_Alo);
    cudaGetSymbolAddress((void**)&Bhi,  g_Bhi);
    cudaGetSymbolAddress((void**)&Blo,  g_Blo);
    cudaGetSymbolAddress((void**)&phi,  g_phi);
    cudaGetSymbolAddress((void**)&plo,  g_plo);
    cudaGetSymbolAddress((void**)&vthi, g_vthi);
    cudaGetSymbolAddress((void**)&vtlo, g_vtlo);

    static bool attr_set = false;
    if (!attr_set) {
        cudaFuncSetAttribute(gemm_bf3,  cudaFuncAttributeMaxDynamicSharedMemorySize, GSM2);
        cudaFuncSetAttribute(scores_tc, cudaFuncAttributeMaxDynamicSharedMemorySize, GSM1);
        cudaFuncSetAttribute(pv_tc,     cudaFuncAttributeMaxDynamicSharedMemorySize, GSM1);
        attr_set = true;
    }

    // 1. h0 = x @ Wi + bi
    cvt_split<<<(TOK * DIN) / 1024, 256>>>(x, Ahi, Alo);
    cvt_wt_t<<<dim3(DMODEL / 32, DIN / 32), dim3(32, 8)>>>(Wi, Bhi, Blo, DIN, DMODEL);
    gemm_bf3<<<dim3(32, 16), 256, GSM2>>>(Ahi, Alo, DIN, Bhi, Blo, DIN,
                                          h0, DMODEL, DIN, bi, nullptr);
    // 2. a = rmsnorm(h0, ln1)
    rmsnorm_k<<<TOK, 256>>>(h0, ln1w, a);
    // 3. q,k,v = a @ {Wq,Wk,Wv}
    cvt_split<<<((size_t)TOK * DMODEL) / 1024, 256>>>(a, Ahi, Alo);
    cvt_wt_t<<<dim3(DMODEL / 32, DMODEL / 32), dim3(32, 8)>>>(Wq, Bhi, Blo, DMODEL, DMODEL);
    gemm_bf3<<<dim3(32, 16), 256, GSM2>>>(Ahi, Alo, DMODEL, Bhi, Blo, DMODEL,
                                          q, DMODEL, DMODEL, nullptr, nullptr);
    cvt_wt_t<<<dim3(DMODEL / 32, DMODEL / 32), dim3(32, 8)>>>(Wk, Bhi, Blo, DMODEL, DMODEL);
    gemm_bf3<<<dim3(32, 16), 256, GSM2>>>(Ahi, Alo, DMODEL, Bhi, Blo, DMODEL,
                                          k, DMODEL, DMODEL, nullptr, nullptr);
    cvt_wt_t<<<dim3(DMODEL / 32, DMODEL / 32), dim3(32, 8)>>>(Wv, Bhi, Blo, DMODEL, DMODEL);
    gemm_bf3<<<dim3(32, 16), 256, GSM2>>>(Ahi, Alo, DMODEL, Bhi, Blo, DMODEL,
                                          v, DMODEL, DMODEL, nullptr, nullptr);
    // 4. attention — all tensor core
    cvt_split<<<((size_t)TOK * DMODEL) / 1024, 256>>>(q, Ahi, Alo);   // q split
    cvt_split<<<((size_t)TOK * DMODEL) / 1024, 256>>>(k, Bhi, Blo);   // k split
    scores_tc<<<dim3(8, 8, 128), 256, GSM1>>>(Ahi, Alo, Bhi, Blo, sc);
    softmax_pk<<<128 * SEQ, 256>>>(sc, phi, plo);
    vtrans_split<<<dim3(4, 32, 128), dim3(32, 8)>>>(v, vthi, vtlo);
    pv_tc<<<dim3(1, 8, 128), 256, GSM1>>>(phi, plo, vthi, vtlo, attn);
    // 7. h = h0 + attn @ Wo
    cvt_split<<<((size_t)TOK * DMODEL) / 1024, 256>>>(attn, Ahi, Alo);
    cvt_wt_t<<<dim3(DMODEL / 32, DMODEL / 32), dim3(32, 8)>>>(Wo, Bhi, Blo, DMODEL, DMODEL);
    gemm_bf3<<<dim3(32, 16), 256, GSM2>>>(Ahi, Alo, DMODEL, Bhi, Blo, DMODEL,
                                          h, DMODEL, DMODEL, nullptr, h0);
    // 8. m = rmsnorm(h, ln2)
    rmsnorm_k<<<TOK, 256>>>(h, ln2w, a);
    // 9. g = m @ Wg ; u = m @ Wu
    cvt_split<<<((size_t)TOK * DMODEL) / 1024, 256>>>(a, Ahi, Alo);
    cvt_wt_t<<<dim3(FFN / 32, DMODEL / 32), dim3(32, 8)>>>(Wg, Bhi, Blo, DMODEL, FFN);
    gemm_bf3<<<dim3(128, 16), 256, GSM2>>>(Ahi, Alo, DMODEL, Bhi, Blo, DMODEL,
                                           gb, FFN, DMODEL, nullptr, nullptr);
    cvt_wt_t<<<dim3(FFN / 32, DMODEL / 32), dim3(32, 8)>>>(Wu, Bhi, Blo, DMODEL, FFN);
    gemm_bf3<<<dim3(128, 16), 256, GSM2>>>(Ahi, Alo, DMODEL, Bhi, Blo, DMODEL,
                                           ub, FFN, DMODEL, nullptr, nullptr);
    // 10. t = silu(g) * u
    silumul_k<<<((size_t)TOK * FFN) / (256 * 4), 256>>>(gb, ub);
    // 11. h = h + t @ Wd
    cvt_split<<<((size_t)TOK * FFN) / 1024, 256>>>(gb, Ahi, Alo);
    cvt_wt_t<<<dim3(DMODEL / 32, FFN / 32), dim3(32, 8)>>>(Wd, Bhi, Blo, FFN, DMODEL);
    gemm_bf3<<<dim3(32, 16), 256, GSM2>>>(Ahi, Alo, FFN, Bhi, Blo, FFN,
                                          h, DMODEL, FFN, nullptr, h);
    // 12-13. router + output
    router_k<<<TOK, 128>>>(h, Wr, br, c);
    colsum_k<<<NOUT, 256>>>(Wout, cs);
    final_k<<<TOK, NOUT>>>(c, cs, bout, out);
}